// round 11
// baseline (speedup 1.0000x reference)
#include <cuda_runtime.h>
#include <cuda_fp16.h>
#include <math.h>

// ---------------- geometry ----------------
#define BB   2
#define LL   4096
#define DM   1024
#define DIN  2048
#define HH   32
#define PP   64
#define NSt  128
#define NCH  2304      // DIN + 2*NSt
#define NPJ  4384      // 2*DIN + 2*NSt + HH
#define CHK  256
#define NC   16        // chunks per batch
#define ROWS 8192      // BB*LL
#define NBC  32        // BB*NC
#define EPSF 1e-5f

// ---------------- scratch (static device memory, alloc-free) ----------------
__device__ __half g_hn_h[(size_t)ROWS * DM];     // normalized input (fp16)
__device__ float g_zx[(size_t)ROWS * NPJ];       // in_proj output
__device__ float g_xBC[(size_t)ROWS * NCH];      // conv+silu output (x | B | C)
__device__ float g_dt[ROWS * HH];                // softplus(dt)
__device__ float g_Acum[NBC * HH * CHK];         // per-chunk inclusive cumsum of dt*A
__device__ float g_cdec[NBC * HH];               // exp(Acum[last]) per (bc,h)
__device__ float g_S[(size_t)NBC * CHK * CHK];   // ST[s*256+l] per (b,c)
__device__ float g_states[(size_t)NBC * HH * PP * NSt];
__device__ float g_prev[(size_t)NBC * HH * PP * NSt];
__device__ float g_y[(size_t)ROWS * DIN];
__device__ __half g_yn_h[(size_t)ROWS * DIN];    // gated-norm output (fp16)
__device__ __half g_w1h[(size_t)DM * NPJ];       // fp16 in_proj_w
__device__ __half g_w2h[(size_t)DIN * DM];       // fp16 out_proj_w

// ---------------- helpers ----------------
__device__ __forceinline__ float blockReduceSum256(float v) {
    __shared__ float red[32];
    int lane = threadIdx.x & 31, wid = threadIdx.x >> 5;
    #pragma unroll
    for (int o = 16; o; o >>= 1) v += __shfl_down_sync(0xffffffffu, v, o);
    if (lane == 0) red[wid] = v;
    __syncthreads();
    v = (threadIdx.x < 8) ? red[threadIdx.x] : 0.f;
    if (wid == 0) {
        #pragma unroll
        for (int o = 4; o; o >>= 1) v += __shfl_down_sync(0xffffffffu, v, o);
        if (lane == 0) red[0] = v;
    }
    __syncthreads();
    return red[0];
}

__device__ __forceinline__ float softplusf(float x) {
    return (x > 20.f) ? x : log1pf(expf(x));
}
__device__ __forceinline__ float siluf(float x) {
    return x / (1.f + expf(-x));
}
__device__ __forceinline__ void mma_fp16(float* d, const unsigned* a, const unsigned* b) {
    asm volatile(
        "mma.sync.aligned.m16n8k16.row.col.f32.f16.f16.f32 "
        "{%0,%1,%2,%3}, {%4,%5,%6,%7}, {%8,%9}, {%0,%1,%2,%3};"
        : "+f"(d[0]), "+f"(d[1]), "+f"(d[2]), "+f"(d[3])
        : "r"(a[0]), "r"(a[1]), "r"(a[2]), "r"(a[3]), "r"(b[0]), "r"(b[1]));
}

// ---------------- 0) weight pre-convert to fp16 ----------------
__global__ __launch_bounds__(256) void k_round_h(
    const float* __restrict__ in, __half* __restrict__ out, int n4)
{
    int i = blockIdx.x * 256 + threadIdx.x;
    if (i < n4) {
        float4 v = ((const float4*)in)[i];
        ((__half2*)out)[2 * i]     = __floats2half2_rn(v.x, v.y);
        ((__half2*)out)[2 * i + 1] = __floats2half2_rn(v.z, v.w);
    }
}

// ---------------- 1) residual add + RMSNorm (fp16 output) ----------------
__global__ __launch_bounds__(256) void k_addnorm(
    const float* __restrict__ hid, const float* __restrict__ resi,
    const float* __restrict__ w, float* __restrict__ resout)
{
    int row = blockIdx.x, t = threadIdx.x;
    size_t off = (size_t)row * DM;
    float4 hv = ((const float4*)(hid + off))[t];
    float4 rv = ((const float4*)(resi + off))[t];
    hv.x += rv.x; hv.y += rv.y; hv.z += rv.z; hv.w += rv.w;
    ((float4*)(resout + off))[t] = hv;
    float s = hv.x*hv.x + hv.y*hv.y + hv.z*hv.z + hv.w*hv.w;
    s = blockReduceSum256(s);
    float sc = rsqrtf(s * (1.0f / DM) + EPSF);
    float4 wv = ((const float4*)w)[t];
    __half2* dst = (__half2*)(g_hn_h + off);
    dst[2 * t]     = __floats2half2_rn(hv.x * sc * wv.x, hv.y * sc * wv.y);
    dst[2 * t + 1] = __floats2half2_rn(hv.z * sc * wv.z, hv.w * sc * wv.w);
}

// ---------------- 2) FP16 tensor-core GEMM, 3-stage cp.async ----------------
// C[M,N] = A[M,K] @ B[K,N], row-major fp16 in, fp32 out.
// 128x128x32 CTA tile, 256 threads = 8 warps (2x4), warp tile 64x32.
// A smem: [128][32] fp16, row padded to 20 words (40 fp16); ldmatrix.x4.
// B smem: [32][128] fp16, 8-fp16 chunk c stored at c^(k&7); ldmatrix.x4.trans.
#define AS_WORDS (128 * 20)
#define BS_WORDS (32 * 64)
#define GEMM_SMEM (3 * (AS_WORDS + BS_WORDS) * 4)
__global__ __launch_bounds__(256, 2) void gemm_fp16(
    const __half* __restrict__ A, const __half* __restrict__ Bm,
    float* __restrict__ C, int M, int N, int K)
{
    extern __shared__ unsigned smemBuf[];
    unsigned* AsBase = smemBuf;
    unsigned* BsBase = smemBuf + 3 * AS_WORDS;

    int tid = threadIdx.x;
    int lane = tid & 31, warp = tid >> 5;
    int warpRow = warp >> 2, warpCol = warp & 3;
    int rowBase = blockIdx.y * 128, colBase = blockIdx.x * 128;

    // staging indices
    int aRow = tid >> 2, aChunk = (tid & 3);      // 64 rows x 4 chunks (8 fp16)
    int bk = tid >> 4, bc = tid & 15;             // 16 k-rows x 16 chunks
    int gid = lane >> 2, tig = lane & 3;

    unsigned asBase = (unsigned)__cvta_generic_to_shared(AsBase);
    unsigned bsBase = (unsigned)__cvta_generic_to_shared(BsBase);

    const __half* aPtr0 = A + (size_t)(rowBase + aRow) * K + aChunk * 8;
    const __half* aPtr1 = A + (size_t)(rowBase + aRow + 64) * K + aChunk * 8;
    int cc = colBase + bc * 8;
    const __half* bPtr0 = Bm + (size_t)bk * N + cc;
    const __half* bPtr1 = Bm + (size_t)(bk + 16) * N + cc;
    int bsz = (cc < N) ? 16 : 0;

    unsigned da0 = asBase + (unsigned)((aRow * 20 + aChunk * 4) << 2);
    unsigned da1 = da0 + (64 * 20 << 2);
    unsigned db0 = bsBase + (unsigned)((bk * 64 + ((bc ^ (bk & 7)) * 4)) << 2);
    unsigned db1 = db0 + (16 * 64 << 2);

    int nIter = K >> 5;

    #define ISSUE(st, k0) do {                                                        \
        unsigned aoff = (unsigned)(st) * (AS_WORDS << 2);                             \
        unsigned boff = (unsigned)(st) * (BS_WORDS << 2);                             \
        asm volatile("cp.async.cg.shared.global [%0], [%1], 16;"                      \
                     :: "r"(da0 + aoff), "l"(aPtr0 + (k0)) : "memory");               \
        asm volatile("cp.async.cg.shared.global [%0], [%1], 16;"                      \
                     :: "r"(da1 + aoff), "l"(aPtr1 + (k0)) : "memory");               \
        asm volatile("cp.async.cg.shared.global [%0], [%1], 16, %2;"                  \
                     :: "r"(db0 + boff), "l"(bPtr0 + (size_t)(k0) * N), "r"(bsz) : "memory"); \
        asm volatile("cp.async.cg.shared.global [%0], [%1], 16, %2;"                  \
                     :: "r"(db1 + boff), "l"(bPtr1 + (size_t)(k0) * N), "r"(bsz) : "memory"); \
        asm volatile("cp.async.commit_group;" ::: "memory");                          \
    } while (0)

    float acc[4][4][4] = {};

    ISSUE(0, 0);
    if (nIter > 1) ISSUE(1, 32);

    // fragment address components
    int a_row_l = (lane & 7) + ((lane >> 3) & 1) * 8;   // row within 16
    int a_koff  = (lane >> 4) * 4;                      // word offset for k-half
    int b_krow  = ((lane >> 3) & 1) * 8 + (lane & 7);   // k within 16
    int b_nchl  = (lane >> 4);                          // chunk offset within n16

    int st = 0;
    for (int it = 0; it < nIter; it++) {
        if (it + 1 < nIter)
            asm volatile("cp.async.wait_group 1;" ::: "memory");
        else
            asm volatile("cp.async.wait_group 0;" ::: "memory");
        __syncthreads();
        if (it + 2 < nIter) {
            int stN = st + 2; if (stN >= 3) stN -= 3;
            ISSUE(stN, (it + 2) << 5);
        }

        unsigned aStage = asBase + (unsigned)(st * (AS_WORDS << 2));
        unsigned bStage = bsBase + (unsigned)(st * (BS_WORDS << 2));

        #pragma unroll
        for (int ks = 0; ks < 2; ks++) {
            unsigned a[4][4], bfr[2][4];
            #pragma unroll
            for (int i = 0; i < 4; i++) {
                int row = warpRow * 64 + i * 16 + a_row_l;
                unsigned addr = aStage + (unsigned)((row * 20 + ks * 8 + a_koff) << 2);
                asm volatile("ldmatrix.sync.aligned.m8n8.x4.shared.b16 {%0,%1,%2,%3}, [%4];"
                    : "=r"(a[i][0]), "=r"(a[i][1]), "=r"(a[i][2]), "=r"(a[i][3])
                    : "r"(addr));
            }
            #pragma unroll
            for (int j2 = 0; j2 < 2; j2++) {
                int kk = ks * 16 + b_krow;
                int nch = warpCol * 4 + j2 * 2 + b_nchl;
                unsigned addr = bStage + (unsigned)((kk * 64 + ((nch ^ (kk & 7)) * 4)) << 2);
                asm volatile("ldmatrix.sync.aligned.m8n8.x4.trans.shared.b16 {%0,%1,%2,%3}, [%4];"
                    : "=r"(bfr[j2][0]), "=r"(bfr[j2][1]), "=r"(bfr[j2][2]), "=r"(bfr[j2][3])
                    : "r"(addr));
            }
            #pragma unroll
            for (int i = 0; i < 4; i++)
                #pragma unroll
                for (int j = 0; j < 4; j++) {
                    unsigned bb[2] = { bfr[j >> 1][(j & 1) * 2], bfr[j >> 1][(j & 1) * 2 + 1] };
                    mma_fp16(acc[i][j], a[i], bb);
                }
        }
        st++; if (st >= 3) st -= 3;
    }
    #undef ISSUE

    #pragma unroll
    for (int i = 0; i < 4; i++) {
        int r0 = rowBase + warpRow * 64 + i * 16 + gid;
        #pragma unroll
        for (int j = 0; j < 4; j++) {
            int ccj = colBase + warpCol * 32 + j * 8 + tig * 2;
            if (ccj < N) {
                *(float2*)(C + (size_t)r0 * N + ccj)       = make_float2(acc[i][j][0], acc[i][j][1]);
                *(float2*)(C + (size_t)(r0 + 8) * N + ccj) = make_float2(acc[i][j][2], acc[i][j][3]);
            }
        }
    }
}

// ---------------- 3) depthwise causal conv (w=4) + bias + SiLU, sliding window ----------------
__global__ __launch_bounds__(256) void k_conv(
    const float* __restrict__ cw, const float* __restrict__ cb)
{
    int ch = blockIdx.x * 256 + threadIdx.x;   // 0..2303
    int rb = blockIdx.y * 64;
    int b = rb >> 12;
    int l0 = rb & 4095;
    float w0 = cw[ch], w1 = cw[NCH + ch], w2 = cw[2 * NCH + ch], w3 = cw[3 * NCH + ch];
    float bias = cb[ch];
    const float* src = g_zx + DIN + ch;
    float x1 = 0.f, x2 = 0.f, x3 = 0.f;
    if (l0 >= 1) x1 = src[(size_t)(b * LL + l0 - 1) * NPJ];
    if (l0 >= 2) x2 = src[(size_t)(b * LL + l0 - 2) * NPJ];
    if (l0 >= 3) x3 = src[(size_t)(b * LL + l0 - 3) * NPJ];
    #pragma unroll 4
    for (int i = 0; i < 64; i++) {
        int l = l0 + i;
        float cur = src[(size_t)(b * LL + l) * NPJ];
        float acc = bias + w3 * cur + w2 * x1 + w1 * x2 + w0 * x3;
        g_xBC[(size_t)(b * LL + l) * NCH + ch] = siluf(acc);
        x3 = x2; x2 = x1; x1 = cur;
    }
}

// ---------------- 4) dt = softplus(raw+bias); per-chunk cumsum of dt*A ----------------
__global__ __launch_bounds__(256) void k_dtscan(
    const float* __restrict__ dtb, const float* __restrict__ alog)
{
    int bc = blockIdx.x, h = blockIdx.y, l = threadIdx.x;
    int b = bc >> 4, c = bc & 15;
    int row = b * LL + c * CHK + l;
    float raw = g_zx[(size_t)row * NPJ + DIN + NCH + h] + dtb[h];
    float dt = softplusf(raw);
    g_dt[row * HH + h] = dt;
    float v = -dt * expf(alog[h]);
    __shared__ float sb[CHK];
    sb[l] = v;
    __syncthreads();
    for (int o = 1; o < CHK; o <<= 1) {
        float add = (l >= o) ? sb[l - o] : 0.f;
        __syncthreads();
        sb[l] += add;
        __syncthreads();
    }
    g_Acum[(bc * HH + h) * CHK + l] = sb[l];
    if (l == CHK - 1) g_cdec[bc * HH + h] = expf(sb[l]);
}

// ---------------- 5) ST[s,l] = sum_n B[s,n]*C[l,n] per (b,c) ----------------
__global__ __launch_bounds__(256) void k_S()
{
    int st = blockIdx.x, lt = blockIdx.y, bc = blockIdx.z;
    int b = bc >> 4, c = bc & 15;
    int rowb = b * LL + c * CHK;
    int s0 = st * 64, l0 = lt * 64;
    __shared__ float Bsm[32][68];
    __shared__ float Csm[32][68];
    int t = threadIdx.x;
    int ts = t >> 4, tg = t & 15;
    float acc[4][4] = {};
    for (int kt = 0; kt < 4; kt++) {
        for (int idx = t; idx < 2048; idx += 256) {
            int n = idx & 31, s = idx >> 5;
            Bsm[n][s] = g_xBC[(size_t)(rowb + s0 + s) * NCH + DIN + kt * 32 + n];
            Csm[n][s] = g_xBC[(size_t)(rowb + l0 + s) * NCH + DIN + NSt + kt * 32 + n];
        }
        __syncthreads();
        #pragma unroll
        for (int n = 0; n < 32; n++) {
            float sv[4], lv[4];
            *(float4*)&sv[0] = *(const float4*)&Bsm[n][ts * 4];
            *(float4*)&lv[0] = *(const float4*)&Csm[n][tg * 4];
            #pragma unroll
            for (int i = 0; i < 4; i++)
                #pragma unroll
                for (int j = 0; j < 4; j++)
                    acc[i][j] += sv[i] * lv[j];
        }
        __syncthreads();
    }
    float* out = g_S + (size_t)bc * CHK * CHK;
    #pragma unroll
    for (int i = 0; i < 4; i++) {
        float4 v = make_float4(acc[i][0], acc[i][1], acc[i][2], acc[i][3]);
        *(float4*)&out[(s0 + ts * 4 + i) * CHK + l0 + tg * 4] = v;
    }
}

// ---------------- 6) states[p,n] = sum_l B[l,n]*exp(Alast-Acum[l])*x[l,p]*dt[l] ----------------
__global__ __launch_bounds__(256) void k_states()
{
    int bc = blockIdx.x, h = blockIdx.y;
    int b = bc >> 4, c = bc & 15;
    int rowb = b * LL + c * CHK;
    const float* Ac = g_Acum + (bc * HH + h) * CHK;
    __shared__ float wsm[32];
    __shared__ float Bs[32][128];
    __shared__ float Xs[32][68];
    int t = threadIdx.x;
    int tn = t & 15, tp = t >> 4;
    float acc[4][8] = {};
    float alast = Ac[CHK - 1];
    for (int lt = 0; lt < 8; lt++) {
        if (t < 32) wsm[t] = expf(alast - Ac[lt * 32 + t]);
        __syncthreads();
        for (int idx = t; idx < 4096; idx += 256) {
            int n = idx & 127, ll = idx >> 7;
            Bs[ll][n] = g_xBC[(size_t)(rowb + lt * 32 + ll) * NCH + DIN + n] * wsm[ll];
        }
        for (int idx = t; idx < 2048; idx += 256) {
            int p = idx & 63, ll = idx >> 6;
            int row = rowb + lt * 32 + ll;
            Xs[ll][p] = g_xBC[(size_t)row * NCH + h * PP + p] * g_dt[row * HH + h];
        }
        __syncthreads();
        #pragma unroll
        for (int ll = 0; ll < 32; ll++) {
            float pr[4], nr[8];
            *(float4*)&pr[0] = *(const float4*)&Xs[ll][tp * 4];
            *(float4*)&nr[0] = *(const float4*)&Bs[ll][tn * 8];
            *(float4*)&nr[4] = *(const float4*)&Bs[ll][tn * 8 + 4];
            #pragma unroll
            for (int i = 0; i < 4; i++)
                #pragma unroll
                for (int j = 0; j < 8; j++)
                    acc[i][j] += pr[i] * nr[j];
        }
        __syncthreads();
    }
    float* out = g_states + (size_t)(bc * HH + h) * PP * NSt;
    #pragma unroll
    for (int i = 0; i < 4; i++) {
        int p = tp * 4 + i;
        *(float4*)&out[p * NSt + tn * 8]     = make_float4(acc[i][0], acc[i][1], acc[i][2], acc[i][3]);
        *(float4*)&out[p * NSt + tn * 8 + 4] = make_float4(acc[i][4], acc[i][5], acc[i][6], acc[i][7]);
    }
}

// ---------------- 7) inter-chunk recurrence ----------------
__global__ __launch_bounds__(256) void k_scan()
{
    int tid = blockIdx.x * 256 + threadIdx.x;  // 524288
    int n = tid & 127;
    int p = (tid >> 7) & 63;
    int h = (tid >> 13) & 31;
    int b = tid >> 18;
    float carry = 0.f;
    for (int c = 0; c < NC; c++) {
        int bc = b * NC + c;
        size_t idx = (size_t)(bc * HH + h) * PP * NSt + p * NSt + n;
        float dec = g_cdec[bc * HH + h];
        g_prev[idx] = carry;
        carry = carry * dec + g_states[idx];
    }
}

// ---------------- 8) Y = Y_off + Y_diag + D*x ----------------
__global__ __launch_bounds__(256) void k_Y(const float* __restrict__ Dp)
{
    int bc = blockIdx.x, h = blockIdx.y;
    int b = bc >> 4, c = bc & 15;
    int rowb = b * LL + c * CHK;
    int t = threadIdx.x;
    int tl = t >> 2, tp = t & 3;
    int l0 = tl * 4;

    __shared__ float Asm[CHK];
    __shared__ float buf[10496];
    float* Csm = buf;                // 32*260 (off phase)
    float* Psm = buf + 8320;         // 32*68
    float* Xs2 = buf;                // 32*68  (diag phase)
    float* Ssm = buf + 2176;         // 32*260

    const float* Ac = g_Acum + (bc * HH + h) * CHK;
    Asm[t] = Ac[t];
    __syncthreads();
    float al[4];
    #pragma unroll
    for (int i = 0; i < 4; i++) al[i] = Asm[l0 + i];
    float rr[4];
    rr[0] = 1.f;
    #pragma unroll
    for (int i = 1; i < 4; i++) rr[i] = expf(al[i] - al[0]);

    float acc[4][16] = {};
    const float* prevp = g_prev + (size_t)(bc * HH + h) * PP * NSt;

    // ---- Y_off ----
    for (int nt = 0; nt < 4; nt++) {
        for (int idx = t; idx < 8192; idx += 256) {
            int n = idx & 31, l = idx >> 5;
            Csm[n * 260 + l] = g_xBC[(size_t)(rowb + l) * NCH + DIN + NSt + nt * 32 + n];
        }
        for (int idx = t; idx < 2048; idx += 256) {
            int n = idx & 31, p = idx >> 5;
            Psm[n * 68 + p] = prevp[p * NSt + nt * 32 + n];
        }
        __syncthreads();
        #pragma unroll
        for (int n = 0; n < 32; n++) {
            float cl[4], pv[16];
            *(float4*)&cl[0] = *(const float4*)&Csm[n * 260 + l0];
            *(float4*)&pv[0]  = *(const float4*)&Psm[n * 68 + tp * 16];
            *(float4*)&pv[4]  = *(const float4*)&Psm[n * 68 + tp * 16 + 4];
            *(float4*)&pv[8]  = *(const float4*)&Psm[n * 68 + tp * 16 + 8];
            *(float4*)&pv[12] = *(const float4*)&Psm[n * 68 + tp * 16 + 12];
            #pragma unroll
            for (int i = 0; i < 4; i++)
                #pragma unroll
                for (int j = 0; j < 16; j++)
                    acc[i][j] += cl[i] * pv[j];
        }
        __syncthreads();
    }
    #pragma unroll
    for (int i = 0; i < 4; i++) {
        float el = expf(al[i]);
        #pragma unroll
        for (int j = 0; j < 16; j++) acc[i][j] *= el;
    }

    // ---- Y_diag ----
    const float* Sp = g_S + (size_t)bc * CHK * CHK;
    for (int st8 = 0; st8 < 8; st8++) {
        int s0 = st8 * 32;
        for (int idx = t; idx < 2048; idx += 256) {
            int p = idx & 63, ss = idx >> 6;
            int row = rowb + s0 + ss;
            Xs2[ss * 68 + p] = g_xBC[(size_t)row * NCH + h * PP + p] * g_dt[row * HH + h];
        }
        for (int idx = t; idx < 2048; idx += 256) {
            int c4 = idx & 63, ss = idx >> 6;
            *(float4*)&Ssm[ss * 260 + c4 * 4] = *(const float4*)&Sp[(s0 + ss) * CHK + c4 * 4];
        }
        __syncthreads();
        int sEnd = l0 + 1 - s0; if (sEnd > 32) sEnd = 32;
        int bEnd = l0 + 4 - s0; if (bEnd > 32) bEnd = 32;
        for (int ss = 0; ss < sEnd; ss++) {
            int s = s0 + ss;
            float e0 = expf(al[0] - Asm[s]);
            float sv[4], w[4], xv[16];
            *(float4*)&sv[0] = *(const float4*)&Ssm[ss * 260 + l0];
            #pragma unroll
            for (int i = 0; i < 4; i++) w[i] = sv[i] * (e0 * rr[i]);
            *(float4*)&xv[0]  = *(const float4*)&Xs2[ss * 68 + tp * 16];
            *(float4*)&xv[4]  = *(const float4*)&Xs2[ss * 68 + tp * 16 + 4];
            *(float4*)&xv[8]  = *(const float4*)&Xs2[ss * 68 + tp * 16 + 8];
            *(float4*)&xv[12] = *(const float4*)&Xs2[ss * 68 + tp * 16 + 12];
            #pragma unroll
            for (int i = 0; i < 4; i++)
                #pragma unroll
                for (int j = 0; j < 16; j++)
                    acc[i][j] += w[i] * xv[j];
        }
        for (int ss = (sEnd > 0 ? sEnd : 0); ss < bEnd; ss++) {
            int s = s0 + ss;
            float as = Asm[s];
            float sv[4], w[4], xv[16];
            *(float4*)&sv[0] = *(const float4*)&Ssm[ss * 260 + l0];
            #pragma unroll
            for (int i = 0; i < 4; i++)
                w[i] = (s <= l0 + i) ? sv[i] * expf(al[i] - as) : 0.f;
            *(float4*)&xv[0]  = *(const float4*)&Xs2[ss * 68 + tp * 16];
            *(float4*)&xv[4]  = *(const float4*)&Xs2[ss * 68 + tp * 16 + 4];
            *(float4*)&xv[8]  = *(const float4*)&Xs2[ss * 68 + tp * 16 + 8];
            *(float4*)&xv[12] = *(const float4*)&Xs2[ss * 68 + tp * 16 + 12];
            #pragma unroll
            for (int i = 0; i < 4; i++)
                #pragma unroll
                for (int j = 0; j < 16; j++)
                    acc[i][j] += w[i] * xv[j];
        }
        __syncthreads();
    }

    // ---- skip term + store ----
    float dh = Dp[h];
    #pragma unroll
    for (int i = 0; i < 4; i++) {
        int row = rowb + l0 + i;
        const float* xr = g_xBC + (size_t)row * NCH + h * PP + tp * 16;
        float* yr = g_y + (size_t)row * DIN + h * PP + tp * 16;
        #pragma unroll
        for (int j4 = 0; j4 < 4; j4++) {
            float4 xv = *(const float4*)(xr + j4 * 4);
            float4 o;
            o.x = acc[i][j4 * 4 + 0] + dh * xv.x;
            o.y = acc[i][j4 * 4 + 1] + dh * xv.y;
            o.z = acc[i][j4 * 4 + 2] + dh * xv.z;
            o.w = acc[i][j4 * 4 + 3] + dh * xv.w;
            *(float4*)(yr + j4 * 4) = o;
        }
    }
}

// ---------------- 9) gated SiLU + RMSNorm over 2048 (fp16 output) ----------------
__global__ __launch_bounds__(256) void k_gatednorm(const float* __restrict__ gw)
{
    int row = blockIdx.x, t = threadIdx.x;
    size_t yo = (size_t)row * DIN;
    size_t zo = (size_t)row * NPJ;
    float4 vv[2];
    float ssum = 0.f;
    #pragma unroll
    for (int k = 0; k < 2; k++) {
        float4 yv = ((const float4*)(g_y + yo))[k * 256 + t];
        float4 zv = ((const float4*)(g_zx + zo))[k * 256 + t];
        float4 v;
        v.x = yv.x * siluf(zv.x); v.y = yv.y * siluf(zv.y);
        v.z = yv.z * siluf(zv.z); v.w = yv.w * siluf(zv.w);
        vv[k] = v;
        ssum += v.x * v.x + v.y * v.y + v.z * v.z + v.w * v.w;
    }
    ssum = blockReduceSum256(ssum);
    float sc = rsqrtf(ssum * (1.0f / DIN) + EPSF);
    __half2* dst = (__half2*)(g_yn_h + yo);
    #pragma unroll
    for (int k = 0; k < 2; k++) {
        float4 w = ((const float4*)gw)[k * 256 + t];
        float4 v = vv[k];
        dst[2 * (k * 256 + t)]     = __floats2half2_rn(v.x * sc * w.x, v.y * sc * w.y);
        dst[2 * (k * 256 + t) + 1] = __floats2half2_rn(v.z * sc * w.z, v.w * sc * w.w);
    }
}

// ---------------- launch ----------------
extern "C" void kernel_launch(void* const* d_in, const int* in_sizes, int n_in,
                              void* d_out, int out_size)
{
    const float* hid  = (const float*)d_in[0];
    const float* resi = (const float*)d_in[1];
    const float* nw   = (const float*)d_in[2];
    const float* inw  = (const float*)d_in[3];
    const float* cw   = (const float*)d_in[4];
    const float* cb   = (const float*)d_in[5];
    const float* dtb  = (const float*)d_in[6];
    const float* alog = (const float*)d_in[7];
    const float* Dp   = (const float*)d_in[8];
    const float* gw   = (const float*)d_in[9];
    const float* ow   = (const float*)d_in[10];

    float* out    = (float*)d_out;
    float* resout = out + (size_t)ROWS * DM;

    float *p_zx;
    __half *p_hn, *p_yn, *p_w1, *p_w2;
    cudaGetSymbolAddress((void**)&p_hn, g_hn_h);
    cudaGetSymbolAddress((void**)&p_zx, g_zx);
    cudaGetSymbolAddress((void**)&p_yn, g_yn_h);
    cudaGetSymbolAddress((void**)&p_w1, g_w1h);
    cudaGetSymbolAddress((void**)&p_w2, g_w2h);

    cudaFuncSetAttribute(gemm_fp16, cudaFuncAttributeMaxDynamicSharedMemorySize, GEMM_SMEM);

    k_round_h<<<(DM * NPJ / 4 + 255) / 256, 256>>>(inw, p_w1, DM * NPJ / 4);
    k_round_h<<<(DIN * DM / 4 + 255) / 256, 256>>>(ow, p_w2, DIN * DM / 4);
    k_addnorm<<<ROWS, 256>>>(hid, resi, nw, resout);
    gemm_fp16<<<dim3((NPJ + 127) / 128, ROWS / 128), 256, GEMM_SMEM>>>(p_hn, p_w1, p_zx, ROWS, NPJ, DM);
    k_conv<<<dim3(NCH / 256, ROWS / 64), 256>>>(cw, cb);
    k_dtscan<<<dim3(NBC, HH), 256>>>(dtb, alog);
    k_S<<<dim3(4, 4, NBC), 256>>>();
    k_states<<<dim3(NBC, HH), 256>>>();
    k_scan<<<(BB * HH * PP * NSt) / 256, 256>>>();
    k_Y<<<dim3(NBC, HH), 256>>>(Dp);
    k_gatednorm<<<ROWS, 256>>>(gw);
    gemm_fp16<<<dim3(DM / 128, ROWS / 128), 256, GEMM_SMEM>>>(p_yn, p_w2, out, ROWS, DM, DIN);
}

// round 12
// speedup vs baseline: 1.0324x; 1.0324x over previous
#include <cuda_runtime.h>
#include <cuda_fp16.h>
#include <math.h>

// ---------------- geometry ----------------
#define BB   2
#define LL   4096
#define DM   1024
#define DIN  2048
#define HH   32
#define PP   64
#define NSt  128
#define NCH  2304      // DIN + 2*NSt
#define NPJ  4384      // 2*DIN + 2*NSt + HH
#define CHK  256
#define NC   16        // chunks per batch
#define ROWS 8192      // BB*LL
#define NBC  32        // BB*NC
#define EPSF 1e-5f

// ---------------- scratch (static device memory, alloc-free) ----------------
__device__ __half g_hn_h[(size_t)ROWS * DM];     // normalized input (fp16)
__device__ float g_zx[(size_t)ROWS * NPJ];       // in_proj output
__device__ float g_xBC[(size_t)ROWS * DIN];      // conv+silu x-part (fp32, for skip term)
__device__ __half g_xBCh[(size_t)ROWS * NCH];    // conv+silu output fp16 (x | B | C)
__device__ float g_dt[ROWS * HH];                // softplus(dt)
__device__ float g_Acum[NBC * HH * CHK];         // per-chunk inclusive cumsum of dt*A
__device__ float g_cdec[NBC * HH];               // exp(Acum[last]) per (bc,h)
__device__ __half g_S_h[(size_t)NBC * CHK * CHK];// ST[s*256+l] per (b,c), fp16
__device__ float g_states[(size_t)NBC * HH * PP * NSt];
__device__ __half g_prev_h[(size_t)NBC * HH * PP * NSt];
__device__ float g_y[(size_t)ROWS * DIN];
__device__ __half g_yn_h[(size_t)ROWS * DIN];    // gated-norm output (fp16)
__device__ __half g_w1h[(size_t)DM * NPJ];       // fp16 in_proj_w
__device__ __half g_w2h[(size_t)DIN * DM];       // fp16 out_proj_w

// ---------------- helpers ----------------
__device__ __forceinline__ float blockReduceSum256(float v) {
    __shared__ float red[32];
    int lane = threadIdx.x & 31, wid = threadIdx.x >> 5;
    #pragma unroll
    for (int o = 16; o; o >>= 1) v += __shfl_down_sync(0xffffffffu, v, o);
    if (lane == 0) red[wid] = v;
    __syncthreads();
    v = (threadIdx.x < 8) ? red[threadIdx.x] : 0.f;
    if (wid == 0) {
        #pragma unroll
        for (int o = 4; o; o >>= 1) v += __shfl_down_sync(0xffffffffu, v, o);
        if (lane == 0) red[0] = v;
    }
    __syncthreads();
    return red[0];
}

__device__ __forceinline__ float softplusf(float x) {
    return (x > 20.f) ? x : log1pf(expf(x));
}
__device__ __forceinline__ float siluf(float x) {
    return x / (1.f + expf(-x));
}
__device__ __forceinline__ void mma_fp16(float* d, const unsigned* a, const unsigned* b) {
    asm volatile(
        "mma.sync.aligned.m16n8k16.row.col.f32.f16.f16.f32 "
        "{%0,%1,%2,%3}, {%4,%5,%6,%7}, {%8,%9}, {%0,%1,%2,%3};"
        : "+f"(d[0]), "+f"(d[1]), "+f"(d[2]), "+f"(d[3])
        : "r"(a[0]), "r"(a[1]), "r"(a[2]), "r"(a[3]), "r"(b[0]), "r"(b[1]));
}
// load 4 fp16 from smem -> 4 fp32
__device__ __forceinline__ void h4f(const __half* p, float* f) {
    uint2 u = *(const uint2*)p;
    float2 a = __half22float2(*(__half2*)&u.x), b = __half22float2(*(__half2*)&u.y);
    f[0] = a.x; f[1] = a.y; f[2] = b.x; f[3] = b.y;
}
// load 8 fp16 from smem -> 8 fp32
__device__ __forceinline__ void h8f(const __half* p, float* f) {
    uint4 u = *(const uint4*)p;
    float2 a = __half22float2(*(__half2*)&u.x), b = __half22float2(*(__half2*)&u.y);
    float2 c = __half22float2(*(__half2*)&u.z), d = __half22float2(*(__half2*)&u.w);
    f[0] = a.x; f[1] = a.y; f[2] = b.x; f[3] = b.y;
    f[4] = c.x; f[5] = c.y; f[6] = d.x; f[7] = d.y;
}

// ---------------- 0) weight pre-convert to fp16 ----------------
__global__ __launch_bounds__(256) void k_round_h(
    const float* __restrict__ in, __half* __restrict__ out, int n4)
{
    int i = blockIdx.x * 256 + threadIdx.x;
    if (i < n4) {
        float4 v = ((const float4*)in)[i];
        ((__half2*)out)[2 * i]     = __floats2half2_rn(v.x, v.y);
        ((__half2*)out)[2 * i + 1] = __floats2half2_rn(v.z, v.w);
    }
}

// ---------------- 1) residual add + RMSNorm (fp16 output) ----------------
__global__ __launch_bounds__(256) void k_addnorm(
    const float* __restrict__ hid, const float* __restrict__ resi,
    const float* __restrict__ w, float* __restrict__ resout)
{
    int row = blockIdx.x, t = threadIdx.x;
    size_t off = (size_t)row * DM;
    float4 hv = ((const float4*)(hid + off))[t];
    float4 rv = ((const float4*)(resi + off))[t];
    hv.x += rv.x; hv.y += rv.y; hv.z += rv.z; hv.w += rv.w;
    ((float4*)(resout + off))[t] = hv;
    float s = hv.x*hv.x + hv.y*hv.y + hv.z*hv.z + hv.w*hv.w;
    s = blockReduceSum256(s);
    float sc = rsqrtf(s * (1.0f / DM) + EPSF);
    float4 wv = ((const float4*)w)[t];
    __half2* dst = (__half2*)(g_hn_h + off);
    dst[2 * t]     = __floats2half2_rn(hv.x * sc * wv.x, hv.y * sc * wv.y);
    dst[2 * t + 1] = __floats2half2_rn(hv.z * sc * wv.z, hv.w * sc * wv.w);
}

// ---------------- 2) FP16 tensor-core GEMM, 3-stage cp.async ----------------
#define AS_WORDS (128 * 20)
#define BS_WORDS (32 * 64)
#define GEMM_SMEM (3 * (AS_WORDS + BS_WORDS) * 4)
__global__ __launch_bounds__(256, 2) void gemm_fp16(
    const __half* __restrict__ A, const __half* __restrict__ Bm,
    float* __restrict__ C, int M, int N, int K)
{
    extern __shared__ unsigned smemBuf[];
    unsigned* AsBase = smemBuf;
    unsigned* BsBase = smemBuf + 3 * AS_WORDS;

    int tid = threadIdx.x;
    int lane = tid & 31, warp = tid >> 5;
    int warpRow = warp >> 2, warpCol = warp & 3;
    int rowBase = blockIdx.y * 128, colBase = blockIdx.x * 128;

    int aRow = tid >> 2, aChunk = (tid & 3);
    int bk = tid >> 4, bc = tid & 15;
    int gid = lane >> 2, tig = lane & 3;

    unsigned asBase = (unsigned)__cvta_generic_to_shared(AsBase);
    unsigned bsBase = (unsigned)__cvta_generic_to_shared(BsBase);

    const __half* aPtr0 = A + (size_t)(rowBase + aRow) * K + aChunk * 8;
    const __half* aPtr1 = A + (size_t)(rowBase + aRow + 64) * K + aChunk * 8;
    int cc = colBase + bc * 8;
    const __half* bPtr0 = Bm + (size_t)bk * N + cc;
    const __half* bPtr1 = Bm + (size_t)(bk + 16) * N + cc;
    int bsz = (cc < N) ? 16 : 0;

    unsigned da0 = asBase + (unsigned)((aRow * 20 + aChunk * 4) << 2);
    unsigned da1 = da0 + (64 * 20 << 2);
    unsigned db0 = bsBase + (unsigned)((bk * 64 + ((bc ^ (bk & 7)) * 4)) << 2);
    unsigned db1 = db0 + (16 * 64 << 2);

    int nIter = K >> 5;

    #define ISSUE(st, k0) do {                                                        \
        unsigned aoff = (unsigned)(st) * (AS_WORDS << 2);                             \
        unsigned boff = (unsigned)(st) * (BS_WORDS << 2);                             \
        asm volatile("cp.async.cg.shared.global [%0], [%1], 16;"                      \
                     :: "r"(da0 + aoff), "l"(aPtr0 + (k0)) : "memory");               \
        asm volatile("cp.async.cg.shared.global [%0], [%1], 16;"                      \
                     :: "r"(da1 + aoff), "l"(aPtr1 + (k0)) : "memory");               \
        asm volatile("cp.async.cg.shared.global [%0], [%1], 16, %2;"                  \
                     :: "r"(db0 + boff), "l"(bPtr0 + (size_t)(k0) * N), "r"(bsz) : "memory"); \
        asm volatile("cp.async.cg.shared.global [%0], [%1], 16, %2;"                  \
                     :: "r"(db1 + boff), "l"(bPtr1 + (size_t)(k0) * N), "r"(bsz) : "memory"); \
        asm volatile("cp.async.commit_group;" ::: "memory");                          \
    } while (0)

    float acc[4][4][4] = {};

    ISSUE(0, 0);
    if (nIter > 1) ISSUE(1, 32);

    int a_row_l = (lane & 7) + ((lane >> 3) & 1) * 8;
    int a_koff  = (lane >> 4) * 4;
    int b_krow  = ((lane >> 3) & 1) * 8 + (lane & 7);
    int b_nchl  = (lane >> 4);

    int st = 0;
    for (int it = 0; it < nIter; it++) {
        if (it + 1 < nIter)
            asm volatile("cp.async.wait_group 1;" ::: "memory");
        else
            asm volatile("cp.async.wait_group 0;" ::: "memory");
        __syncthreads();
        if (it + 2 < nIter) {
            int stN = st + 2; if (stN >= 3) stN -= 3;
            ISSUE(stN, (it + 2) << 5);
        }

        unsigned aStage = asBase + (unsigned)(st * (AS_WORDS << 2));
        unsigned bStage = bsBase + (unsigned)(st * (BS_WORDS << 2));

        #pragma unroll
        for (int ks = 0; ks < 2; ks++) {
            unsigned a[4][4], bfr[2][4];
            #pragma unroll
            for (int i = 0; i < 4; i++) {
                int row = warpRow * 64 + i * 16 + a_row_l;
                unsigned addr = aStage + (unsigned)((row * 20 + ks * 8 + a_koff) << 2);
                asm volatile("ldmatrix.sync.aligned.m8n8.x4.shared.b16 {%0,%1,%2,%3}, [%4];"
                    : "=r"(a[i][0]), "=r"(a[i][1]), "=r"(a[i][2]), "=r"(a[i][3])
                    : "r"(addr));
            }
            #pragma unroll
            for (int j2 = 0; j2 < 2; j2++) {
                int kk = ks * 16 + b_krow;
                int nch = warpCol * 4 + j2 * 2 + b_nchl;
                unsigned addr = bStage + (unsigned)((kk * 64 + ((nch ^ (kk & 7)) * 4)) << 2);
                asm volatile("ldmatrix.sync.aligned.m8n8.x4.trans.shared.b16 {%0,%1,%2,%3}, [%4];"
                    : "=r"(bfr[j2][0]), "=r"(bfr[j2][1]), "=r"(bfr[j2][2]), "=r"(bfr[j2][3])
                    : "r"(addr));
            }
            #pragma unroll
            for (int i = 0; i < 4; i++)
                #pragma unroll
                for (int j = 0; j < 4; j++) {
                    unsigned bb[2] = { bfr[j >> 1][(j & 1) * 2], bfr[j >> 1][(j & 1) * 2 + 1] };
                    mma_fp16(acc[i][j], a[i], bb);
                }
        }
        st++; if (st >= 3) st -= 3;
    }
    #undef ISSUE

    #pragma unroll
    for (int i = 0; i < 4; i++) {
        int r0 = rowBase + warpRow * 64 + i * 16 + gid;
        #pragma unroll
        for (int j = 0; j < 4; j++) {
            int ccj = colBase + warpCol * 32 + j * 8 + tig * 2;
            if (ccj < N) {
                *(float2*)(C + (size_t)r0 * N + ccj)       = make_float2(acc[i][j][0], acc[i][j][1]);
                *(float2*)(C + (size_t)(r0 + 8) * N + ccj) = make_float2(acc[i][j][2], acc[i][j][3]);
            }
        }
    }
}

// ---------------- 3) depthwise causal conv + bias + SiLU (fp32 x + fp16 all) ----------------
__global__ __launch_bounds__(256) void k_conv(
    const float* __restrict__ cw, const float* __restrict__ cb)
{
    int ch = blockIdx.x * 256 + threadIdx.x;   // 0..2303
    int rb = blockIdx.y * 64;
    int b = rb >> 12;
    int l0 = rb & 4095;
    float w0 = cw[ch], w1 = cw[NCH + ch], w2 = cw[2 * NCH + ch], w3 = cw[3 * NCH + ch];
    float bias = cb[ch];
    const float* src = g_zx + DIN + ch;
    float x1 = 0.f, x2 = 0.f, x3 = 0.f;
    if (l0 >= 1) x1 = src[(size_t)(b * LL + l0 - 1) * NPJ];
    if (l0 >= 2) x2 = src[(size_t)(b * LL + l0 - 2) * NPJ];
    if (l0 >= 3) x3 = src[(size_t)(b * LL + l0 - 3) * NPJ];
    #pragma unroll 4
    for (int i = 0; i < 64; i++) {
        int l = l0 + i;
        float cur = src[(size_t)(b * LL + l) * NPJ];
        float v = siluf(bias + w3 * cur + w2 * x1 + w1 * x2 + w0 * x3);
        if (ch < DIN) g_xBC[(size_t)(b * LL + l) * DIN + ch] = v;
        g_xBCh[(size_t)(b * LL + l) * NCH + ch] = __float2half(v);
        x3 = x2; x2 = x1; x1 = cur;
    }
}

// ---------------- 4) dt = softplus(raw+bias); per-chunk cumsum of dt*A ----------------
__global__ __launch_bounds__(256) void k_dtscan(
    const float* __restrict__ dtb, const float* __restrict__ alog)
{
    int bc = blockIdx.x, h = blockIdx.y, l = threadIdx.x;
    int b = bc >> 4, c = bc & 15;
    int row = b * LL + c * CHK + l;
    float raw = g_zx[(size_t)row * NPJ + DIN + NCH + h] + dtb[h];
    float dt = softplusf(raw);
    g_dt[row * HH + h] = dt;
    float v = -dt * expf(alog[h]);
    __shared__ float sb[CHK];
    sb[l] = v;
    __syncthreads();
    for (int o = 1; o < CHK; o <<= 1) {
        float add = (l >= o) ? sb[l - o] : 0.f;
        __syncthreads();
        sb[l] += add;
        __syncthreads();
    }
    g_Acum[(bc * HH + h) * CHK + l] = sb[l];
    if (l == CHK - 1) g_cdec[bc * HH + h] = expf(sb[l]);
}

// ---------------- 5) ST[s,l] = sum_n B[s,n]*C[l,n] per (b,c), fp16 operands ----------------
__global__ __launch_bounds__(256) void k_S()
{
    int st = blockIdx.x, lt = blockIdx.y, bc = blockIdx.z;
    int b = bc >> 4, c = bc & 15;
    int rowb = b * LL + c * CHK;
    int s0 = st * 64, l0 = lt * 64;
    __shared__ __half Bsm[32 * 72];
    __shared__ __half Csm[32 * 72];
    int t = threadIdx.x;
    int ts = t >> 4, tg = t & 15;
    float acc[4][4] = {};
    for (int kt = 0; kt < 4; kt++) {
        for (int idx = t; idx < 2048; idx += 256) {
            int n = idx & 31, s = idx >> 5;
            Bsm[n * 72 + s] = g_xBCh[(size_t)(rowb + s0 + s) * NCH + DIN + kt * 32 + n];
            Csm[n * 72 + s] = g_xBCh[(size_t)(rowb + l0 + s) * NCH + DIN + NSt + kt * 32 + n];
        }
        __syncthreads();
        #pragma unroll
        for (int n = 0; n < 32; n++) {
            float sv[4], lv[4];
            h4f(&Bsm[n * 72 + ts * 4], sv);
            h4f(&Csm[n * 72 + tg * 4], lv);
            #pragma unroll
            for (int i = 0; i < 4; i++)
                #pragma unroll
                for (int j = 0; j < 4; j++)
                    acc[i][j] += sv[i] * lv[j];
        }
        __syncthreads();
    }
    __half* out = g_S_h + (size_t)bc * CHK * CHK;
    #pragma unroll
    for (int i = 0; i < 4; i++) {
        uint2 u;
        *(__half2*)&u.x = __floats2half2_rn(acc[i][0], acc[i][1]);
        *(__half2*)&u.y = __floats2half2_rn(acc[i][2], acc[i][3]);
        *(uint2*)&out[(s0 + ts * 4 + i) * CHK + l0 + tg * 4] = u;
    }
}

// ---------------- 6) states[p,n] = sum_l B[l,n]*exp(Alast-Acum[l])*x[l,p]*dt[l] ----------------
__global__ __launch_bounds__(256) void k_states()
{
    int bc = blockIdx.x, h = blockIdx.y;
    int b = bc >> 4, c = bc & 15;
    int rowb = b * LL + c * CHK;
    const float* Ac = g_Acum + (bc * HH + h) * CHK;
    __shared__ float wsm[32];
    __shared__ __half Bs[32 * 136];
    __shared__ __half Xs[32 * 72];
    int t = threadIdx.x;
    int tn = t & 15, tp = t >> 4;
    float acc[4][8] = {};
    float alast = Ac[CHK - 1];
    const __half2* xbc2 = (const __half2*)g_xBCh;
    for (int lt = 0; lt < 8; lt++) {
        if (t < 32) wsm[t] = expf(alast - Ac[lt * 32 + t]);
        __syncthreads();
        for (int idx = t; idx < 2048; idx += 256) {
            int n2 = idx & 63, ll = idx >> 6;
            int row = rowb + lt * 32 + ll;
            __half2 v = xbc2[(size_t)row * (NCH / 2) + (DIN / 2) + n2];
            __half2 w = __float2half2_rn(wsm[ll]);
            *(__half2*)&Bs[ll * 136 + n2 * 2] = __hmul2(v, w);
        }
        for (int idx = t; idx < 1024; idx += 256) {
            int p2 = idx & 31, ll = idx >> 5;
            int row = rowb + lt * 32 + ll;
            __half2 v = xbc2[(size_t)row * (NCH / 2) + h * 32 + p2];
            __half2 d = __float2half2_rn(g_dt[row * HH + h]);
            *(__half2*)&Xs[ll * 72 + p2 * 2] = __hmul2(v, d);
        }
        __syncthreads();
        #pragma unroll
        for (int ll = 0; ll < 32; ll++) {
            float pr[4], nr[8];
            h4f(&Xs[ll * 72 + tp * 4], pr);
            h8f(&Bs[ll * 136 + tn * 8], nr);
            #pragma unroll
            for (int i = 0; i < 4; i++)
                #pragma unroll
                for (int j = 0; j < 8; j++)
                    acc[i][j] += pr[i] * nr[j];
        }
        __syncthreads();
    }
    float* out = g_states + (size_t)(bc * HH + h) * PP * NSt;
    #pragma unroll
    for (int i = 0; i < 4; i++) {
        int p = tp * 4 + i;
        *(float4*)&out[p * NSt + tn * 8]     = make_float4(acc[i][0], acc[i][1], acc[i][2], acc[i][3]);
        *(float4*)&out[p * NSt + tn * 8 + 4] = make_float4(acc[i][4], acc[i][5], acc[i][6], acc[i][7]);
    }
}

// ---------------- 7) inter-chunk recurrence (fp32 carry, fp16 prev out) ----------------
__global__ __launch_bounds__(256) void k_scan()
{
    int tid = blockIdx.x * 256 + threadIdx.x;  // 524288
    int n = tid & 127;
    int p = (tid >> 7) & 63;
    int h = (tid >> 13) & 31;
    int b = tid >> 18;
    float carry = 0.f;
    for (int c = 0; c < NC; c++) {
        int bc = b * NC + c;
        size_t idx = (size_t)(bc * HH + h) * PP * NSt + p * NSt + n;
        float dec = g_cdec[bc * HH + h];
        g_prev_h[idx] = __float2half(carry);
        carry = carry * dec + g_states[idx];
    }
}

// ---------------- 8) Y = Y_off + Y_diag + D*x (fp16 operands, fp32 accum) ----------------
__global__ __launch_bounds__(256) void k_Y(const float* __restrict__ Dp)
{
    int bc = blockIdx.x, h = blockIdx.y;
    int b = bc >> 4, c = bc & 15;
    int rowb = b * LL + c * CHK;
    int t = threadIdx.x;
    int tl = t >> 2, tp = t & 3;
    int l0 = tl * 4;

    __shared__ float Asm[CHK];
    __shared__ __half buf[10752];
    __half* Csm = buf;               // 32*264 = 8448 (off phase)
    __half* Psm = buf + 8448;        // 32*72  = 2304
    __half* Xs2 = buf;               // 32*72  = 2304 (diag phase)
    __half* Ssm = buf + 2304;        // 32*264 = 8448

    const float* Ac = g_Acum + (bc * HH + h) * CHK;
    Asm[t] = Ac[t];
    __syncthreads();
    float al[4];
    #pragma unroll
    for (int i = 0; i < 4; i++) al[i] = Asm[l0 + i];
    float rr[4];
    rr[0] = 1.f;
    #pragma unroll
    for (int i = 1; i < 4; i++) rr[i] = expf(al[i] - al[0]);

    float acc[4][16] = {};
    const __half* prevp = g_prev_h + (size_t)(bc * HH + h) * PP * NSt;

    // ---- Y_off: acc[l,p] = sum_n C[l,n] * prev[p,n] ----
    for (int nt = 0; nt < 4; nt++) {
        for (int idx = t; idx < 8192; idx += 256) {
            int n = idx & 31, l = idx >> 5;
            Csm[n * 264 + l] = g_xBCh[(size_t)(rowb + l) * NCH + DIN + NSt + nt * 32 + n];
        }
        for (int idx = t; idx < 2048; idx += 256) {
            int n = idx & 31, p = idx >> 5;
            Psm[n * 72 + p] = prevp[p * NSt + nt * 32 + n];
        }
        __syncthreads();
        #pragma unroll
        for (int n = 0; n < 32; n++) {
            float cl[4], pv[16];
            h4f(&Csm[n * 264 + l0], cl);
            h8f(&Psm[n * 72 + tp * 16], pv);
            h8f(&Psm[n * 72 + tp * 16 + 8], pv + 8);
            #pragma unroll
            for (int i = 0; i < 4; i++)
                #pragma unroll
                for (int j = 0; j < 16; j++)
                    acc[i][j] += cl[i] * pv[j];
        }
        __syncthreads();
    }
    #pragma unroll
    for (int i = 0; i < 4; i++) {
        float el = expf(al[i]);
        #pragma unroll
        for (int j = 0; j < 16; j++) acc[i][j] *= el;
    }

    // ---- Y_diag: acc[l,p] += sum_{s<=l} ST[s,l]*exp(Acum[l]-Acum[s])*xdt[s,p] ----
    const __half* Sp = g_S_h + (size_t)bc * CHK * CHK;
    const __half2* xbc2 = (const __half2*)g_xBCh;
    for (int st8 = 0; st8 < 8; st8++) {
        int s0 = st8 * 32;
        for (int idx = t; idx < 1024; idx += 256) {
            int p2 = idx & 31, ss = idx >> 5;
            int row = rowb + s0 + ss;
            __half2 v = xbc2[(size_t)row * (NCH / 2) + h * 32 + p2];
            __half2 d = __float2half2_rn(g_dt[row * HH + h]);
            *(__half2*)&Xs2[ss * 72 + p2 * 2] = __hmul2(v, d);
        }
        for (int idx = t; idx < 4096; idx += 256) {   // 32 rows x 128 uints (256 halves)
            int l2 = idx & 127, ss = idx >> 7;
            ((unsigned*)&Ssm[ss * 264])[l2] = ((const unsigned*)&Sp[(s0 + ss) * CHK])[l2];
        }
        __syncthreads();
        int sEnd = l0 + 1 - s0; if (sEnd > 32) sEnd = 32;
        int bEnd = l0 + 4 - s0; if (bEnd > 32) bEnd = 32;
        for (int ss = 0; ss < sEnd; ss++) {
            int s = s0 + ss;
            float e0 = expf(al[0] - Asm[s]);
            float sv[4], w[4], xv[16];
            h4f(&Ssm[ss * 264 + l0], sv);
            #pragma unroll
            for (int i = 0; i < 4; i++) w[i] = sv[i] * (e0 * rr[i]);
            h8f(&Xs2[ss * 72 + tp * 16], xv);
            h8f(&Xs2[ss * 72 + tp * 16 + 8], xv + 8);
            #pragma unroll
            for (int i = 0; i < 4; i++)
                #pragma unroll
                for (int j = 0; j < 16; j++)
                    acc[i][j] += w[i] * xv[j];
        }
        for (int ss = (sEnd > 0 ? sEnd : 0); ss < bEnd; ss++) {
            int s = s0 + ss;
            float as = Asm[s];
            float sv[4], w[4], xv[16];
            h4f(&Ssm[ss * 264 + l0], sv);
            #pragma unroll
            for (int i = 0; i < 4; i++)
                w[i] = (s <= l0 + i) ? sv[i] * expf(al[i] - as) : 0.f;
            h8f(&Xs2[ss * 72 + tp * 16], xv);
            h8f(&Xs2[ss * 72 + tp * 16 + 8], xv + 8);
            #pragma unroll
            for (int i = 0; i < 4; i++)
                #pragma unroll
                for (int j = 0; j < 16; j++)
                    acc[i][j] += w[i] * xv[j];
        }
        __syncthreads();
    }

    // ---- skip term (exact fp32 x) + store ----
    float dh = Dp[h];
    #pragma unroll
    for (int i = 0; i < 4; i++) {
        int row = rowb + l0 + i;
        const float* xr = g_xBC + (size_t)row * DIN + h * PP + tp * 16;
        float* yr = g_y + (size_t)row * DIN + h * PP + tp * 16;
        #pragma unroll
        for (int j4 = 0; j4 < 4; j4++) {
            float4 xv = *(const float4*)(xr + j4 * 4);
            float4 o;
            o.x = acc[i][j4 * 4 + 0] + dh * xv.x;
            o.y = acc[i][j4 * 4 + 1] + dh * xv.y;
            o.z = acc[i][j4 * 4 + 2] + dh * xv.z;
            o.w = acc[i][j4 * 4 + 3] + dh * xv.w;
            *(float4*)(yr + j4 * 4) = o;
        }
    }
}

// ---------------- 9) gated SiLU + RMSNorm over 2048 (fp16 output) ----------------
__global__ __launch_bounds__(256) void k_gatednorm(const float* __restrict__ gw)
{
    int row = blockIdx.x, t = threadIdx.x;
    size_t yo = (size_t)row * DIN;
    size_t zo = (size_t)row * NPJ;
    float4 vv[2];
    float ssum = 0.f;
    #pragma unroll
    for (int k = 0; k < 2; k++) {
        float4 yv = ((const float4*)(g_y + yo))[k * 256 + t];
        float4 zv = ((const float4*)(g_zx + zo))[k * 256 + t];
        float4 v;
        v.x = yv.x * siluf(zv.x); v.y = yv.y * siluf(zv.y);
        v.z = yv.z * siluf(zv.z); v.w = yv.w * siluf(zv.w);
        vv[k] = v;
        ssum += v.x * v.x + v.y * v.y + v.z * v.z + v.w * v.w;
    }
    ssum = blockReduceSum256(ssum);
    float sc = rsqrtf(ssum * (1.0f / DIN) + EPSF);
    __half2* dst = (__half2*)(g_yn_h + yo);
    #pragma unroll
    for (int k = 0; k < 2; k++) {
        float4 w = ((const float4*)gw)[k * 256 + t];
        float4 v = vv[k];
        dst[2 * (k * 256 + t)]     = __floats2half2_rn(v.x * sc * w.x, v.y * sc * w.y);
        dst[2 * (k * 256 + t) + 1] = __floats2half2_rn(v.z * sc * w.z, v.w * sc * w.w);
    }
}

// ---------------- launch ----------------
extern "C" void kernel_launch(void* const* d_in, const int* in_sizes, int n_in,
                              void* d_out, int out_size)
{
    const float* hid  = (const float*)d_in[0];
    const float* resi = (const float*)d_in[1];
    const float* nw   = (const float*)d_in[2];
    const float* inw  = (const float*)d_in[3];
    const float* cw   = (const float*)d_in[4];
    const float* cb   = (const float*)d_in[5];
    const float* dtb  = (const float*)d_in[6];
    const float* alog = (const float*)d_in[7];
    const float* Dp   = (const float*)d_in[8];
    const float* gw   = (const float*)d_in[9];
    const float* ow   = (const float*)d_in[10];

    float* out    = (float*)d_out;
    float* resout = out + (size_t)ROWS * DM;

    float *p_zx;
    __half *p_hn, *p_yn, *p_w1, *p_w2;
    cudaGetSymbolAddress((void**)&p_hn, g_hn_h);
    cudaGetSymbolAddress((void**)&p_zx, g_zx);
    cudaGetSymbolAddress((void**)&p_yn, g_yn_h);
    cudaGetSymbolAddress((void**)&p_w1, g_w1h);
    cudaGetSymbolAddress((void**)&p_w2, g_w2h);

    cudaFuncSetAttribute(gemm_fp16, cudaFuncAttributeMaxDynamicSharedMemorySize, GEMM_SMEM);

    k_round_h<<<(DM * NPJ / 4 + 255) / 256, 256>>>(inw, p_w1, DM * NPJ / 4);
    k_round_h<<<(DIN * DM / 4 + 255) / 256, 256>>>(ow, p_w2, DIN * DM / 4);
    k_addnorm<<<ROWS, 256>>>(hid, resi, nw, resout);
    gemm_fp16<<<dim3((NPJ + 127) / 128, ROWS / 128), 256, GEMM_SMEM>>>(p_hn, p_w1, p_zx, ROWS, NPJ, DM);
    k_conv<<<dim3(NCH / 256, ROWS / 64), 256>>>(cw, cb);
    k_dtscan<<<dim3(NBC, HH), 256>>>(dtb, alog);
    k_S<<<dim3(4, 4, NBC), 256>>>();
    k_states<<<dim3(NBC, HH), 256>>>();
    k_scan<<<(BB * HH * PP * NSt) / 256, 256>>>();
    k_Y<<<dim3(NBC, HH), 256>>>(Dp);
    k_gatednorm<<<ROWS, 256>>>(gw);
    gemm_fp16<<<dim3(DM / 128, ROWS / 128), 256, GEMM_SMEM>>>(p_yn, p_w2, out, ROWS, DM, DIN);
}

// round 13
// speedup vs baseline: 2.0547x; 1.9902x over previous
#include <cuda_runtime.h>
#include <cuda_fp16.h>
#include <math.h>

// ---------------- geometry ----------------
#define BB   2
#define LL   4096
#define DM   1024
#define DIN  2048
#define HH   32
#define PP   64
#define NSt  128
#define NCH  2304      // DIN + 2*NSt
#define NPJ  4384      // 2*DIN + 2*NSt + HH
#define CHK  256
#define NC   16        // chunks per batch
#define ROWS 8192      // BB*LL
#define NBC  32        // BB*NC
#define EPSF 1e-5f

// ---------------- scratch (static device memory, alloc-free) ----------------
__device__ __half g_hn_h[(size_t)ROWS * DM];     // normalized input (fp16)
__device__ float g_zx[(size_t)ROWS * NPJ];       // in_proj output
__device__ float g_xBC[(size_t)ROWS * DIN];      // conv+silu x-part (fp32, for skip term)
__device__ __half g_xBCh[(size_t)ROWS * NCH];    // conv+silu output fp16 (x | B | C)
__device__ float g_dt[ROWS * HH];                // softplus(dt)
__device__ float g_Acum[NBC * HH * CHK];         // per-chunk inclusive cumsum of dt*A
__device__ float g_cdec[NBC * HH];               // exp(Acum[last]) per (bc,h)
__device__ __half g_S_h[(size_t)NBC * CHK * CHK];// ST[s*256+l] per (b,c), fp16
__device__ float g_states[(size_t)NBC * HH * PP * NSt];
__device__ __half g_prev_h[(size_t)NBC * HH * PP * NSt];
__device__ float g_y[(size_t)ROWS * DIN];
__device__ __half g_yn_h[(size_t)ROWS * DIN];    // gated-norm output (fp16)
__device__ __half g_w1h[(size_t)DM * NPJ];       // fp16 in_proj_w
__device__ __half g_w2h[(size_t)DIN * DM];       // fp16 out_proj_w

// ---------------- helpers ----------------
__device__ __forceinline__ float blockReduceSum256(float v) {
    __shared__ float red[32];
    int lane = threadIdx.x & 31, wid = threadIdx.x >> 5;
    #pragma unroll
    for (int o = 16; o; o >>= 1) v += __shfl_down_sync(0xffffffffu, v, o);
    if (lane == 0) red[wid] = v;
    __syncthreads();
    v = (threadIdx.x < 8) ? red[threadIdx.x] : 0.f;
    if (wid == 0) {
        #pragma unroll
        for (int o = 4; o; o >>= 1) v += __shfl_down_sync(0xffffffffu, v, o);
        if (lane == 0) red[0] = v;
    }
    __syncthreads();
    return red[0];
}

__device__ __forceinline__ float softplusf(float x) {
    return (x > 20.f) ? x : log1pf(expf(x));
}
__device__ __forceinline__ float siluf(float x) {
    return x / (1.f + expf(-x));
}
__device__ __forceinline__ void mma_fp16(float* d, const unsigned* a, const unsigned* b) {
    asm volatile(
        "mma.sync.aligned.m16n8k16.row.col.f32.f16.f16.f32 "
        "{%0,%1,%2,%3}, {%4,%5,%6,%7}, {%8,%9}, {%0,%1,%2,%3};"
        : "+f"(d[0]), "+f"(d[1]), "+f"(d[2]), "+f"(d[3])
        : "r"(a[0]), "r"(a[1]), "r"(a[2]), "r"(a[3]), "r"(b[0]), "r"(b[1]));
}
#define LDSM_X4(dst, addr) \
    asm volatile("ldmatrix.sync.aligned.m8n8.x4.shared.b16 {%0,%1,%2,%3}, [%4];" \
        : "=r"((dst)[0]), "=r"((dst)[1]), "=r"((dst)[2]), "=r"((dst)[3]) : "r"(addr))
#define LDSM_X4T(dst, addr) \
    asm volatile("ldmatrix.sync.aligned.m8n8.x4.trans.shared.b16 {%0,%1,%2,%3}, [%4];" \
        : "=r"((dst)[0]), "=r"((dst)[1]), "=r"((dst)[2]), "=r"((dst)[3]) : "r"(addr))

// ---------------- 0) weight pre-convert to fp16 ----------------
__global__ __launch_bounds__(256) void k_round_h(
    const float* __restrict__ in, __half* __restrict__ out, int n4)
{
    int i = blockIdx.x * 256 + threadIdx.x;
    if (i < n4) {
        float4 v = ((const float4*)in)[i];
        ((__half2*)out)[2 * i]     = __floats2half2_rn(v.x, v.y);
        ((__half2*)out)[2 * i + 1] = __floats2half2_rn(v.z, v.w);
    }
}

// ---------------- 1) residual add + RMSNorm (fp16 output) ----------------
__global__ __launch_bounds__(256) void k_addnorm(
    const float* __restrict__ hid, const float* __restrict__ resi,
    const float* __restrict__ w, float* __restrict__ resout)
{
    int row = blockIdx.x, t = threadIdx.x;
    size_t off = (size_t)row * DM;
    float4 hv = ((const float4*)(hid + off))[t];
    float4 rv = ((const float4*)(resi + off))[t];
    hv.x += rv.x; hv.y += rv.y; hv.z += rv.z; hv.w += rv.w;
    ((float4*)(resout + off))[t] = hv;
    float s = hv.x*hv.x + hv.y*hv.y + hv.z*hv.z + hv.w*hv.w;
    s = blockReduceSum256(s);
    float sc = rsqrtf(s * (1.0f / DM) + EPSF);
    float4 wv = ((const float4*)w)[t];
    __half2* dst = (__half2*)(g_hn_h + off);
    dst[2 * t]     = __floats2half2_rn(hv.x * sc * wv.x, hv.y * sc * wv.y);
    dst[2 * t + 1] = __floats2half2_rn(hv.z * sc * wv.z, hv.w * sc * wv.w);
}

// ---------------- 2) FP16 tensor-core GEMM, 3-stage cp.async ----------------
#define AS_WORDS (128 * 20)
#define BS_WORDS (32 * 64)
#define GEMM_SMEM (3 * (AS_WORDS + BS_WORDS) * 4)
__global__ __launch_bounds__(256, 2) void gemm_fp16(
    const __half* __restrict__ A, const __half* __restrict__ Bm,
    float* __restrict__ C, int M, int N, int K)
{
    extern __shared__ unsigned smemBuf[];
    unsigned* AsBase = smemBuf;
    unsigned* BsBase = smemBuf + 3 * AS_WORDS;

    int tid = threadIdx.x;
    int lane = tid & 31, warp = tid >> 5;
    int warpRow = warp >> 2, warpCol = warp & 3;
    int rowBase = blockIdx.y * 128, colBase = blockIdx.x * 128;

    int aRow = tid >> 2, aChunk = (tid & 3);
    int bk = tid >> 4, bc = tid & 15;
    int gid = lane >> 2, tig = lane & 3;

    unsigned asBase = (unsigned)__cvta_generic_to_shared(AsBase);
    unsigned bsBase = (unsigned)__cvta_generic_to_shared(BsBase);

    const __half* aPtr0 = A + (size_t)(rowBase + aRow) * K + aChunk * 8;
    const __half* aPtr1 = A + (size_t)(rowBase + aRow + 64) * K + aChunk * 8;
    int cc = colBase + bc * 8;
    const __half* bPtr0 = Bm + (size_t)bk * N + cc;
    const __half* bPtr1 = Bm + (size_t)(bk + 16) * N + cc;
    int bsz = (cc < N) ? 16 : 0;

    unsigned da0 = asBase + (unsigned)((aRow * 20 + aChunk * 4) << 2);
    unsigned da1 = da0 + (64 * 20 << 2);
    unsigned db0 = bsBase + (unsigned)((bk * 64 + ((bc ^ (bk & 7)) * 4)) << 2);
    unsigned db1 = db0 + (16 * 64 << 2);

    int nIter = K >> 5;

    #define ISSUE(st, k0) do {                                                        \
        unsigned aoff = (unsigned)(st) * (AS_WORDS << 2);                             \
        unsigned boff = (unsigned)(st) * (BS_WORDS << 2);                             \
        asm volatile("cp.async.cg.shared.global [%0], [%1], 16;"                      \
                     :: "r"(da0 + aoff), "l"(aPtr0 + (k0)) : "memory");               \
        asm volatile("cp.async.cg.shared.global [%0], [%1], 16;"                      \
                     :: "r"(da1 + aoff), "l"(aPtr1 + (k0)) : "memory");               \
        asm volatile("cp.async.cg.shared.global [%0], [%1], 16, %2;"                  \
                     :: "r"(db0 + boff), "l"(bPtr0 + (size_t)(k0) * N), "r"(bsz) : "memory"); \
        asm volatile("cp.async.cg.shared.global [%0], [%1], 16, %2;"                  \
                     :: "r"(db1 + boff), "l"(bPtr1 + (size_t)(k0) * N), "r"(bsz) : "memory"); \
        asm volatile("cp.async.commit_group;" ::: "memory");                          \
    } while (0)

    float acc[4][4][4] = {};

    ISSUE(0, 0);
    if (nIter > 1) ISSUE(1, 32);

    int a_row_l = (lane & 7) + ((lane >> 3) & 1) * 8;
    int a_koff  = (lane >> 4) * 4;
    int b_krow  = ((lane >> 3) & 1) * 8 + (lane & 7);
    int b_nchl  = (lane >> 4);

    int st = 0;
    for (int it = 0; it < nIter; it++) {
        if (it + 1 < nIter)
            asm volatile("cp.async.wait_group 1;" ::: "memory");
        else
            asm volatile("cp.async.wait_group 0;" ::: "memory");
        __syncthreads();
        if (it + 2 < nIter) {
            int stN = st + 2; if (stN >= 3) stN -= 3;
            ISSUE(stN, (it + 2) << 5);
        }

        unsigned aStage = asBase + (unsigned)(st * (AS_WORDS << 2));
        unsigned bStage = bsBase + (unsigned)(st * (BS_WORDS << 2));

        #pragma unroll
        for (int ks = 0; ks < 2; ks++) {
            unsigned a[4][4], bfr[2][4];
            #pragma unroll
            for (int i = 0; i < 4; i++) {
                int row = warpRow * 64 + i * 16 + a_row_l;
                unsigned addr = aStage + (unsigned)((row * 20 + ks * 8 + a_koff) << 2);
                LDSM_X4(a[i], addr);
            }
            #pragma unroll
            for (int j2 = 0; j2 < 2; j2++) {
                int kk = ks * 16 + b_krow;
                int nch = warpCol * 4 + j2 * 2 + b_nchl;
                unsigned addr = bStage + (unsigned)((kk * 64 + ((nch ^ (kk & 7)) * 4)) << 2);
                LDSM_X4T(bfr[j2], addr);
            }
            #pragma unroll
            for (int i = 0; i < 4; i++)
                #pragma unroll
                for (int j = 0; j < 4; j++) {
                    unsigned bb[2] = { bfr[j >> 1][(j & 1) * 2], bfr[j >> 1][(j & 1) * 2 + 1] };
                    mma_fp16(acc[i][j], a[i], bb);
                }
        }
        st++; if (st >= 3) st -= 3;
    }
    #undef ISSUE

    #pragma unroll
    for (int i = 0; i < 4; i++) {
        int r0 = rowBase + warpRow * 64 + i * 16 + gid;
        #pragma unroll
        for (int j = 0; j < 4; j++) {
            int ccj = colBase + warpCol * 32 + j * 8 + tig * 2;
            if (ccj < N) {
                *(float2*)(C + (size_t)r0 * N + ccj)       = make_float2(acc[i][j][0], acc[i][j][1]);
                *(float2*)(C + (size_t)(r0 + 8) * N + ccj) = make_float2(acc[i][j][2], acc[i][j][3]);
            }
        }
    }
}

// ---------------- 3) depthwise causal conv + bias + SiLU ----------------
__global__ __launch_bounds__(256) void k_conv(
    const float* __restrict__ cw, const float* __restrict__ cb)
{
    int ch = blockIdx.x * 256 + threadIdx.x;   // 0..2303
    int rb = blockIdx.y * 64;
    int b = rb >> 12;
    int l0 = rb & 4095;
    float w0 = cw[ch], w1 = cw[NCH + ch], w2 = cw[2 * NCH + ch], w3 = cw[3 * NCH + ch];
    float bias = cb[ch];
    const float* src = g_zx + DIN + ch;
    float x1 = 0.f, x2 = 0.f, x3 = 0.f;
    if (l0 >= 1) x1 = src[(size_t)(b * LL + l0 - 1) * NPJ];
    if (l0 >= 2) x2 = src[(size_t)(b * LL + l0 - 2) * NPJ];
    if (l0 >= 3) x3 = src[(size_t)(b * LL + l0 - 3) * NPJ];
    #pragma unroll 4
    for (int i = 0; i < 64; i++) {
        int l = l0 + i;
        float cur = src[(size_t)(b * LL + l) * NPJ];
        float v = siluf(bias + w3 * cur + w2 * x1 + w1 * x2 + w0 * x3);
        if (ch < DIN) g_xBC[(size_t)(b * LL + l) * DIN + ch] = v;
        g_xBCh[(size_t)(b * LL + l) * NCH + ch] = __float2half(v);
        x3 = x2; x2 = x1; x1 = cur;
    }
}

// ---------------- 4) dt = softplus(raw+bias); per-chunk cumsum of dt*A ----------------
__global__ __launch_bounds__(256) void k_dtscan(
    const float* __restrict__ dtb, const float* __restrict__ alog)
{
    int bc = blockIdx.x, h = blockIdx.y, l = threadIdx.x;
    int b = bc >> 4, c = bc & 15;
    int row = b * LL + c * CHK + l;
    float raw = g_zx[(size_t)row * NPJ + DIN + NCH + h] + dtb[h];
    float dt = softplusf(raw);
    g_dt[row * HH + h] = dt;
    float v = -dt * expf(alog[h]);
    __shared__ float sb[CHK];
    sb[l] = v;
    __syncthreads();
    for (int o = 1; o < CHK; o <<= 1) {
        float add = (l >= o) ? sb[l - o] : 0.f;
        __syncthreads();
        sb[l] += add;
        __syncthreads();
    }
    g_Acum[(bc * HH + h) * CHK + l] = sb[l];
    if (l == CHK - 1) g_cdec[bc * HH + h] = expf(sb[l]);
}

// ---------------- 5) ST[s,l] = sum_n B[s,n]*C[l,n] per (b,c), fp16 operands ----------------
__global__ __launch_bounds__(256) void k_S()
{
    int st = blockIdx.x, lt = blockIdx.y, bc = blockIdx.z;
    int b = bc >> 4, c = bc & 15;
    int rowb = b * LL + c * CHK;
    int s0 = st * 64, l0 = lt * 64;
    __shared__ __half Bsm[32 * 72];
    __shared__ __half Csm[32 * 72];
    int t = threadIdx.x;
    int ts = t >> 4, tg = t & 15;
    float acc[4][4] = {};
    for (int kt = 0; kt < 4; kt++) {
        for (int idx = t; idx < 2048; idx += 256) {
            int n = idx & 31, s = idx >> 5;
            Bsm[n * 72 + s] = g_xBCh[(size_t)(rowb + s0 + s) * NCH + DIN + kt * 32 + n];
            Csm[n * 72 + s] = g_xBCh[(size_t)(rowb + l0 + s) * NCH + DIN + NSt + kt * 32 + n];
        }
        __syncthreads();
        #pragma unroll
        for (int n = 0; n < 32; n++) {
            float sv[4], lv[4];
            {
                uint2 u = *(const uint2*)&Bsm[n * 72 + ts * 4];
                float2 a = __half22float2(*(__half2*)&u.x), b2 = __half22float2(*(__half2*)&u.y);
                sv[0] = a.x; sv[1] = a.y; sv[2] = b2.x; sv[3] = b2.y;
            }
            {
                uint2 u = *(const uint2*)&Csm[n * 72 + tg * 4];
                float2 a = __half22float2(*(__half2*)&u.x), b2 = __half22float2(*(__half2*)&u.y);
                lv[0] = a.x; lv[1] = a.y; lv[2] = b2.x; lv[3] = b2.y;
            }
            #pragma unroll
            for (int i = 0; i < 4; i++)
                #pragma unroll
                for (int j = 0; j < 4; j++)
                    acc[i][j] += sv[i] * lv[j];
        }
        __syncthreads();
    }
    __half* out = g_S_h + (size_t)bc * CHK * CHK;
    #pragma unroll
    for (int i = 0; i < 4; i++) {
        uint2 u;
        *(__half2*)&u.x = __floats2half2_rn(acc[i][0], acc[i][1]);
        *(__half2*)&u.y = __floats2half2_rn(acc[i][2], acc[i][3]);
        *(uint2*)&out[(s0 + ts * 4 + i) * CHK + l0 + tg * 4] = u;
    }
}

// ---------------- 6) states via MMA: states[p,n] = sum_l Xdt[l,p]*Bw[l,n] ----------------
// m=64(p) n=128(n) k=256(l). A = Xdt^T staged [p][l-tile], B = Bw [l][n] trans path.
__global__ __launch_bounds__(256) void k_states()
{
    int bc = blockIdx.x, h = blockIdx.y;
    int b = bc >> 4, c = bc & 15;
    int rowb = b * LL + c * CHK;
    const float* Ac = g_Acum + (bc * HH + h) * CHK;
    __shared__ float wsm[32];
    __shared__ __half Xt[64 * 40];     // [p][l] stride 40
    __shared__ __half Bw[32 * 136];    // [l][n] stride 136
    int t = threadIdx.x;
    int lane = t & 31, warp = t >> 5;
    int mb = (warp >> 1) * 16, nb = (warp & 1) * 64;
    int a_row_l = (lane & 7) + ((lane >> 3) & 1) * 8;
    int a_koff  = (lane >> 4) * 8;                    // halves
    int b_krow  = ((lane >> 3) & 1) * 8 + (lane & 7);
    int b_nchl  = (lane >> 4);
    int gid = lane >> 2, tig = lane & 3;
    unsigned xtB = (unsigned)__cvta_generic_to_shared(Xt);
    unsigned bwB = (unsigned)__cvta_generic_to_shared(Bw);

    float acc[8][4] = {};
    float alast = Ac[CHK - 1];
    const __half2* xbc2 = (const __half2*)g_xBCh;
    for (int lt = 0; lt < 8; lt++) {
        if (t < 32) wsm[t] = __expf(alast - Ac[lt * 32 + t]);
        __syncthreads();
        // stage Bw [ll][n]
        for (int idx = t; idx < 2048; idx += 256) {
            int n2 = idx & 63, ll = idx >> 6;
            int row = rowb + lt * 32 + ll;
            __half2 v = xbc2[(size_t)row * (NCH / 2) + (DIN / 2) + n2];
            __half2 w = __float2half2_rn(wsm[ll]);
            *(__half2*)&Bw[ll * 136 + n2 * 2] = __hmul2(v, w);
        }
        // stage Xt [p][ll] (transpose)
        for (int idx = t; idx < 1024; idx += 256) {
            int p2 = idx & 31, ll = idx >> 5;
            int row = rowb + lt * 32 + ll;
            __half2 v = xbc2[(size_t)row * (NCH / 2) + h * 32 + p2];
            __half2 d = __float2half2_rn(g_dt[row * HH + h]);
            __half2 r = __hmul2(v, d);
            Xt[(p2 * 2) * 40 + ll]     = __low2half(r);
            Xt[(p2 * 2 + 1) * 40 + ll] = __high2half(r);
        }
        __syncthreads();
        #pragma unroll
        for (int ks = 0; ks < 2; ks++) {
            unsigned a[4], bfr[4][4];
            {
                int row = mb + a_row_l;
                unsigned addr = xtB + (unsigned)((row * 40 + ks * 16 + a_koff) * 2);
                LDSM_X4(a, addr);
            }
            #pragma unroll
            for (int j2 = 0; j2 < 4; j2++) {
                int kk = ks * 16 + b_krow;
                int nch = (nb >> 3) + j2 * 2 + b_nchl;
                unsigned addr = bwB + (unsigned)((kk * 136 + nch * 8) * 2);
                LDSM_X4T(bfr[j2], addr);
            }
            #pragma unroll
            for (int j = 0; j < 8; j++) {
                unsigned bb[2] = { bfr[j >> 1][(j & 1) * 2], bfr[j >> 1][(j & 1) * 2 + 1] };
                mma_fp16(acc[j], a, bb);
            }
        }
        __syncthreads();
    }
    float* out = g_states + (size_t)(bc * HH + h) * PP * NSt;
    #pragma unroll
    for (int j = 0; j < 8; j++) {
        int p0 = mb + gid;
        int nn = nb + j * 8 + tig * 2;
        *(float2*)&out[p0 * NSt + nn]       = make_float2(acc[j][0], acc[j][1]);
        *(float2*)&out[(p0 + 8) * NSt + nn] = make_float2(acc[j][2], acc[j][3]);
    }
}

// ---------------- 7) inter-chunk recurrence (fp32 carry, fp16 prev out) ----------------
__global__ __launch_bounds__(256) void k_scan()
{
    int tid = blockIdx.x * 256 + threadIdx.x;  // 524288
    int n = tid & 127;
    int p = (tid >> 7) & 63;
    int h = (tid >> 13) & 31;
    int b = tid >> 18;
    float carry = 0.f;
    for (int c = 0; c < NC; c++) {
        int bc = b * NC + c;
        size_t idx = (size_t)(bc * HH + h) * PP * NSt + p * NSt + n;
        float dec = g_cdec[bc * HH + h];
        g_prev_h[idx] = __float2half(carry);
        carry = carry * dec + g_states[idx];
    }
}

// ---------------- 8) Y = Y_off + Y_diag + D*x via MMA ----------------
// Y[l=256][p=64]. off: A=C[l][n] direct, B=prev^T staged [n][p]; scale exp(Acum[l]).
// diag: A=M[l][s] materialized (masked decay*S), B=Xdt[s][p] trans path.
__global__ __launch_bounds__(256) void k_Y(const float* __restrict__ Dp)
{
    int bc = blockIdx.x, h = blockIdx.y;
    int b = bc >> 4, c = bc & 15;
    int rowb = b * LL + c * CHK;
    int t = threadIdx.x;
    int lane = t & 31, warp = t >> 5;
    int mb = (warp >> 1) * 64, nb = (warp & 1) * 32;

    __shared__ float Asm[CHK];
    __shared__ __half Am[256 * 40];    // Ct (off) / Msm (diag), stride 40
    __shared__ __half Bt[32 * 72];     // Pt (off) / Xs2 (diag), stride 72

    const float* Ac = g_Acum + (bc * HH + h) * CHK;
    Asm[t] = Ac[t];

    int a_row_l = (lane & 7) + ((lane >> 3) & 1) * 8;
    int a_koff  = (lane >> 4) * 8;
    int b_krow  = ((lane >> 3) & 1) * 8 + (lane & 7);
    int b_nchl  = (lane >> 4);
    int gid = lane >> 2, tig = lane & 3;
    unsigned amB = (unsigned)__cvta_generic_to_shared(Am);
    unsigned btB = (unsigned)__cvta_generic_to_shared(Bt);

    float acc[4][4][4] = {};
    const __half2* xbc2 = (const __half2*)g_xBCh;
    const __half* prevp = g_prev_h + (size_t)(bc * HH + h) * PP * NSt;
    __syncthreads();

    // ---- off phase: k = n_state, 4 tiles of 32 ----
    for (int nt = 0; nt < 4; nt++) {
        for (int idx = t; idx < 4096; idx += 256) {       // Ct[l][kk]
            int kk2 = idx & 15, l = idx >> 4;
            __half2 v = xbc2[(size_t)(rowb + l) * (NCH / 2) + (DIN + NSt) / 2 + nt * 16 + kk2];
            *(__half2*)&Am[l * 40 + kk2 * 2] = v;
        }
        for (int idx = t; idx < 1024; idx += 256) {       // Pt[kk][p] transpose
            int kk2 = idx & 15, p = idx >> 4;
            __half2 v = *(const __half2*)&prevp[p * NSt + nt * 32 + kk2 * 2];
            Bt[(kk2 * 2) * 72 + p]     = __low2half(v);
            Bt[(kk2 * 2 + 1) * 72 + p] = __high2half(v);
        }
        __syncthreads();
        #pragma unroll
        for (int ks = 0; ks < 2; ks++) {
            unsigned a[4][4], bfr[2][4];
            #pragma unroll
            for (int i = 0; i < 4; i++) {
                int row = mb + i * 16 + a_row_l;
                unsigned addr = amB + (unsigned)((row * 40 + ks * 16 + a_koff) * 2);
                LDSM_X4(a[i], addr);
            }
            #pragma unroll
            for (int j2 = 0; j2 < 2; j2++) {
                int kk = ks * 16 + b_krow;
                int nch = (nb >> 3) + j2 * 2 + b_nchl;
                unsigned addr = btB + (unsigned)((kk * 72 + nch * 8) * 2);
                LDSM_X4T(bfr[j2], addr);
            }
            #pragma unroll
            for (int i = 0; i < 4; i++)
                #pragma unroll
                for (int j = 0; j < 4; j++) {
                    unsigned bb[2] = { bfr[j >> 1][(j & 1) * 2], bfr[j >> 1][(j & 1) * 2 + 1] };
                    mma_fp16(acc[i][j], a[i], bb);
                }
        }
        __syncthreads();
    }
    // scale off result by exp(Acum[l])
    #pragma unroll
    for (int i = 0; i < 4; i++) {
        int l0 = mb + i * 16 + gid;
        float e0 = __expf(Asm[l0]);
        float e1 = __expf(Asm[l0 + 8]);
        #pragma unroll
        for (int j = 0; j < 4; j++) {
            acc[i][j][0] *= e0; acc[i][j][1] *= e0;
            acc[i][j][2] *= e1; acc[i][j][3] *= e1;
        }
    }

    // ---- diag phase: k = s, 8 tiles of 32 ----
    const __half* Sp = g_S_h + (size_t)bc * CHK * CHK;
    float alv = Asm[t];
    for (int st8 = 0; st8 < 8; st8++) {
        int s0 = st8 * 32;
        // materialize M[l=t][ss] = S[s][l]*exp(Acum[l]-Acum[s])*(s<=l)
        #pragma unroll 4
        for (int ss = 0; ss < 32; ss++) {
            int s = s0 + ss;
            float w = 0.f;
            if (s <= t)
                w = __half2float(Sp[(size_t)s * CHK + t]) * __expf(alv - Asm[s]);
            Am[t * 40 + ss] = __float2half(w);
        }
        // stage Xs2[ss][p]
        for (int idx = t; idx < 1024; idx += 256) {
            int p2 = idx & 31, ss = idx >> 5;
            int row = rowb + s0 + ss;
            __half2 v = xbc2[(size_t)row * (NCH / 2) + h * 32 + p2];
            __half2 d = __float2half2_rn(g_dt[row * HH + h]);
            *(__half2*)&Bt[ss * 72 + p2 * 2] = __hmul2(v, d);
        }
        __syncthreads();
        if (mb + 64 > s0) {
            #pragma unroll
            for (int ks = 0; ks < 2; ks++) {
                unsigned a[4][4], bfr[2][4];
                #pragma unroll
                for (int i = 0; i < 4; i++) {
                    int row = mb + i * 16 + a_row_l;
                    unsigned addr = amB + (unsigned)((row * 40 + ks * 16 + a_koff) * 2);
                    LDSM_X4(a[i], addr);
                }
                #pragma unroll
                for (int j2 = 0; j2 < 2; j2++) {
                    int kk = ks * 16 + b_krow;
                    int nch = (nb >> 3) + j2 * 2 + b_nchl;
                    unsigned addr = btB + (unsigned)((kk * 72 + nch * 8) * 2);
                    LDSM_X4T(bfr[j2], addr);
                }
                #pragma unroll
                for (int i = 0; i < 4; i++)
                    #pragma unroll
                    for (int j = 0; j < 4; j++) {
                        unsigned bb[2] = { bfr[j >> 1][(j & 1) * 2], bfr[j >> 1][(j & 1) * 2 + 1] };
                        mma_fp16(acc[i][j], a[i], bb);
                    }
            }
        }
        __syncthreads();
    }

    // ---- skip term (fp32 x) + store ----
    float dh = Dp[h];
    #pragma unroll
    for (int i = 0; i < 4; i++) {
        int l0 = mb + i * 16 + gid;
        #pragma unroll
        for (int j = 0; j < 4; j++) {
            int p = nb + j * 8 + tig * 2;
            #pragma unroll
            for (int r = 0; r < 2; r++) {
                int row = rowb + l0 + r * 8;
                float2 xv = *(const float2*)&g_xBC[(size_t)row * DIN + h * PP + p];
                float2 o;
                o.x = acc[i][j][r * 2 + 0] + dh * xv.x;
                o.y = acc[i][j][r * 2 + 1] + dh * xv.y;
                *(float2*)&g_y[(size_t)row * DIN + h * PP + p] = o;
            }
        }
    }
}

// ---------------- 9) gated SiLU + RMSNorm over 2048 (fp16 output) ----------------
__global__ __launch_bounds__(256) void k_gatednorm(const float* __restrict__ gw)
{
    int row = blockIdx.x, t = threadIdx.x;
    size_t yo = (size_t)row * DIN;
    size_t zo = (size_t)row * NPJ;
    float4 vv[2];
    float ssum = 0.f;
    #pragma unroll
    for (int k = 0; k < 2; k++) {
        float4 yv = ((const float4*)(g_y + yo))[k * 256 + t];
        float4 zv = ((const float4*)(g_zx + zo))[k * 256 + t];
        float4 v;
        v.x = yv.x * siluf(zv.x); v.y = yv.y * siluf(zv.y);
        v.z = yv.z * siluf(zv.z); v.w = yv.w * siluf(zv.w);
        vv[k] = v;
        ssum += v.x * v.x + v.y * v.y + v.z * v.z + v.w * v.w;
    }
    ssum = blockReduceSum256(ssum);
    float sc = rsqrtf(ssum * (1.0f / DIN) + EPSF);
    __half2* dst = (__half2*)(g_yn_h + yo);
    #pragma unroll
    for (int k = 0; k < 2; k++) {
        float4 w = ((const float4*)gw)[k * 256 + t];
        float4 v = vv[k];
        dst[2 * (k * 256 + t)]     = __floats2half2_rn(v.x * sc * w.x, v.y * sc * w.y);
        dst[2 * (k * 256 + t) + 1] = __floats2half2_rn(v.z * sc * w.z, v.w * sc * w.w);
    }
}

// ---------------- launch ----------------
extern "C" void kernel_launch(void* const* d_in, const int* in_sizes, int n_in,
                              void* d_out, int out_size)
{
    const float* hid  = (const float*)d_in[0];
    const float* resi = (const float*)d_in[1];
    const float* nw   = (const float*)d_in[2];
    const float* inw  = (const float*)d_in[3];
    const float* cw   = (const float*)d_in[4];
    const float* cb   = (const float*)d_in[5];
    const float* dtb  = (const float*)d_in[6];
    const float* alog = (const float*)d_in[7];
    const float* Dp   = (const float*)d_in[8];
    const float* gw   = (const float*)d_in[9];
    const float* ow   = (const float*)d_in[10];

    float* out    = (float*)d_out;
    float* resout = out + (size_t)ROWS * DM;

    float *p_zx;
    __half *p_hn, *p_yn, *p_w1, *p_w2;
    cudaGetSymbolAddress((void**)&p_hn, g_hn_h);
    cudaGetSymbolAddress((void**)&p_zx, g_zx);
    cudaGetSymbolAddress((void**)&p_yn, g_yn_h);
    cudaGetSymbolAddress((void**)&p_w1, g_w1h);
    cudaGetSymbolAddress((void**)&p_w2, g_w2h);

    cudaFuncSetAttribute(gemm_fp16, cudaFuncAttributeMaxDynamicSharedMemorySize, GEMM_SMEM);

    k_round_h<<<(DM * NPJ / 4 + 255) / 256, 256>>>(inw, p_w1, DM * NPJ / 4);
    k_round_h<<<(DIN * DM / 4 + 255) / 256, 256>>>(ow, p_w2, DIN * DM / 4);
    k_addnorm<<<ROWS, 256>>>(hid, resi, nw, resout);
    gemm_fp16<<<dim3((NPJ + 127) / 128, ROWS / 128), 256, GEMM_SMEM>>>(p_hn, p_w1, p_zx, ROWS, NPJ, DM);
    k_conv<<<dim3(NCH / 256, ROWS / 64), 256>>>(cw, cb);
    k_dtscan<<<dim3(NBC, HH), 256>>>(dtb, alog);
    k_S<<<dim3(4, 4, NBC), 256>>>();
    k_states<<<dim3(NBC, HH), 256>>>();
    k_scan<<<(BB * HH * PP * NSt) / 256, 256>>>();
    k_Y<<<dim3(NBC, HH), 256>>>(Dp);
    k_gatednorm<<<ROWS, 256>>>(gw);
    gemm_fp16<<<dim3(DM / 128, ROWS / 128), 256, GEMM_SMEM>>>(p_yn, p_w2, out, ROWS, DM, DIN);
}

// round 14
// speedup vs baseline: 2.3006x; 1.1197x over previous
#include <cuda_runtime.h>
#include <cuda_fp16.h>
#include <math.h>

// ---------------- geometry ----------------
#define BB   2
#define LL   4096
#define DM   1024
#define DIN  2048
#define HH   32
#define PP   64
#define NSt  128
#define NCH  2304      // DIN + 2*NSt
#define NPJ  4384      // 2*DIN + 2*NSt + HH
#define CHK  256
#define NC   16        // chunks per batch
#define ROWS 8192      // BB*LL
#define NBC  32        // BB*NC
#define EPSF 1e-5f

// ---------------- scratch (static device memory, alloc-free) ----------------
__device__ __half g_hn_h[(size_t)ROWS * DM];     // normalized input (fp16)
__device__ float g_zx[(size_t)ROWS * NPJ];       // in_proj output
__device__ __half g_xBCh[(size_t)ROWS * NCH];    // conv+silu output fp16 (x | B | C)
__device__ float g_dt[ROWS * HH];                // softplus(dt)
__device__ float g_Acum[NBC * HH * CHK];         // per-chunk inclusive cumsum of dt*A
__device__ float g_cdec[NBC * HH];               // exp(Acum[last]) per (bc,h)
__device__ __half g_S_h[(size_t)NBC * CHK * CHK];// ST[s*256+l] per (b,c), fp16
__device__ float g_states[(size_t)NBC * HH * PP * NSt];
__device__ __half g_prev_h[(size_t)NBC * HH * PP * NSt];
__device__ __half g_y_h[(size_t)ROWS * DIN];     // SSD output (fp16)
__device__ __half g_yn_h[(size_t)ROWS * DIN];    // gated-norm output (fp16)
__device__ __half g_w1h[(size_t)DM * NPJ];       // fp16 in_proj_w
__device__ __half g_w2h[(size_t)DIN * DM];       // fp16 out_proj_w

// ---------------- helpers ----------------
__device__ __forceinline__ float blockReduceSum256(float v) {
    __shared__ float red[32];
    int lane = threadIdx.x & 31, wid = threadIdx.x >> 5;
    #pragma unroll
    for (int o = 16; o; o >>= 1) v += __shfl_down_sync(0xffffffffu, v, o);
    if (lane == 0) red[wid] = v;
    __syncthreads();
    v = (threadIdx.x < 8) ? red[threadIdx.x] : 0.f;
    if (wid == 0) {
        #pragma unroll
        for (int o = 4; o; o >>= 1) v += __shfl_down_sync(0xffffffffu, v, o);
        if (lane == 0) red[0] = v;
    }
    __syncthreads();
    return red[0];
}

__device__ __forceinline__ float softplusf(float x) {
    return (x > 20.f) ? x : log1pf(expf(x));
}
__device__ __forceinline__ float siluf(float x) {
    return x / (1.f + expf(-x));
}
__device__ __forceinline__ void mma_fp16(float* d, const unsigned* a, const unsigned* b) {
    asm volatile(
        "mma.sync.aligned.m16n8k16.row.col.f32.f16.f16.f32 "
        "{%0,%1,%2,%3}, {%4,%5,%6,%7}, {%8,%9}, {%0,%1,%2,%3};"
        : "+f"(d[0]), "+f"(d[1]), "+f"(d[2]), "+f"(d[3])
        : "r"(a[0]), "r"(a[1]), "r"(a[2]), "r"(a[3]), "r"(b[0]), "r"(b[1]));
}
#define LDSM_X4(dst, addr) \
    asm volatile("ldmatrix.sync.aligned.m8n8.x4.shared.b16 {%0,%1,%2,%3}, [%4];" \
        : "=r"((dst)[0]), "=r"((dst)[1]), "=r"((dst)[2]), "=r"((dst)[3]) : "r"(addr))
#define LDSM_X4T(dst, addr) \
    asm volatile("ldmatrix.sync.aligned.m8n8.x4.trans.shared.b16 {%0,%1,%2,%3}, [%4];" \
        : "=r"((dst)[0]), "=r"((dst)[1]), "=r"((dst)[2]), "=r"((dst)[3]) : "r"(addr))

// ---------------- 0) weight pre-convert to fp16 ----------------
__global__ __launch_bounds__(256) void k_round_h(
    const float* __restrict__ in, __half* __restrict__ out, int n4)
{
    int i = blockIdx.x * 256 + threadIdx.x;
    if (i < n4) {
        float4 v = ((const float4*)in)[i];
        ((__half2*)out)[2 * i]     = __floats2half2_rn(v.x, v.y);
        ((__half2*)out)[2 * i + 1] = __floats2half2_rn(v.z, v.w);
    }
}

// ---------------- 1) residual add + RMSNorm (fp16 output) ----------------
__global__ __launch_bounds__(256) void k_addnorm(
    const float* __restrict__ hid, const float* __restrict__ resi,
    const float* __restrict__ w, float* __restrict__ resout)
{
    int row = blockIdx.x, t = threadIdx.x;
    size_t off = (size_t)row * DM;
    float4 hv = ((const float4*)(hid + off))[t];
    float4 rv = ((const float4*)(resi + off))[t];
    hv.x += rv.x; hv.y += rv.y; hv.z += rv.z; hv.w += rv.w;
    ((float4*)(resout + off))[t] = hv;
    float s = hv.x*hv.x + hv.y*hv.y + hv.z*hv.z + hv.w*hv.w;
    s = blockReduceSum256(s);
    float sc = rsqrtf(s * (1.0f / DM) + EPSF);
    float4 wv = ((const float4*)w)[t];
    __half2* dst = (__half2*)(g_hn_h + off);
    dst[2 * t]     = __floats2half2_rn(hv.x * sc * wv.x, hv.y * sc * wv.y);
    dst[2 * t + 1] = __floats2half2_rn(hv.z * sc * wv.z, hv.w * sc * wv.w);
}

// ---------------- 2) FP16 tensor-core GEMM, 3-stage cp.async ----------------
#define AS_WORDS (128 * 20)
#define BS_WORDS (32 * 64)
#define GEMM_SMEM (3 * (AS_WORDS + BS_WORDS) * 4)
__global__ __launch_bounds__(256, 2) void gemm_fp16(
    const __half* __restrict__ A, const __half* __restrict__ Bm,
    float* __restrict__ C, int M, int N, int K)
{
    extern __shared__ unsigned smemBuf[];
    unsigned* AsBase = smemBuf;
    unsigned* BsBase = smemBuf + 3 * AS_WORDS;

    int tid = threadIdx.x;
    int lane = tid & 31, warp = tid >> 5;
    int warpRow = warp >> 2, warpCol = warp & 3;
    int rowBase = blockIdx.y * 128, colBase = blockIdx.x * 128;

    int aRow = tid >> 2, aChunk = (tid & 3);
    int bk = tid >> 4, bc = tid & 15;
    int gid = lane >> 2, tig = lane & 3;

    unsigned asBase = (unsigned)__cvta_generic_to_shared(AsBase);
    unsigned bsBase = (unsigned)__cvta_generic_to_shared(BsBase);

    const __half* aPtr0 = A + (size_t)(rowBase + aRow) * K + aChunk * 8;
    const __half* aPtr1 = A + (size_t)(rowBase + aRow + 64) * K + aChunk * 8;
    int cc = colBase + bc * 8;
    const __half* bPtr0 = Bm + (size_t)bk * N + cc;
    const __half* bPtr1 = Bm + (size_t)(bk + 16) * N + cc;
    int bsz = (cc < N) ? 16 : 0;

    unsigned da0 = asBase + (unsigned)((aRow * 20 + aChunk * 4) << 2);
    unsigned da1 = da0 + (64 * 20 << 2);
    unsigned db0 = bsBase + (unsigned)((bk * 64 + ((bc ^ (bk & 7)) * 4)) << 2);
    unsigned db1 = db0 + (16 * 64 << 2);

    int nIter = K >> 5;

    #define ISSUE(st, k0) do {                                                        \
        unsigned aoff = (unsigned)(st) * (AS_WORDS << 2);                             \
        unsigned boff = (unsigned)(st) * (BS_WORDS << 2);                             \
        asm volatile("cp.async.cg.shared.global [%0], [%1], 16;"                      \
                     :: "r"(da0 + aoff), "l"(aPtr0 + (k0)) : "memory");               \
        asm volatile("cp.async.cg.shared.global [%0], [%1], 16;"                      \
                     :: "r"(da1 + aoff), "l"(aPtr1 + (k0)) : "memory");               \
        asm volatile("cp.async.cg.shared.global [%0], [%1], 16, %2;"                  \
                     :: "r"(db0 + boff), "l"(bPtr0 + (size_t)(k0) * N), "r"(bsz) : "memory"); \
        asm volatile("cp.async.cg.shared.global [%0], [%1], 16, %2;"                  \
                     :: "r"(db1 + boff), "l"(bPtr1 + (size_t)(k0) * N), "r"(bsz) : "memory"); \
        asm volatile("cp.async.commit_group;" ::: "memory");                          \
    } while (0)

    float acc[4][4][4] = {};

    ISSUE(0, 0);
    if (nIter > 1) ISSUE(1, 32);

    int a_row_l = (lane & 7) + ((lane >> 3) & 1) * 8;
    int a_koff  = (lane >> 4) * 4;
    int b_krow  = ((lane >> 3) & 1) * 8 + (lane & 7);
    int b_nchl  = (lane >> 4);

    int st = 0;
    for (int it = 0; it < nIter; it++) {
        if (it + 1 < nIter)
            asm volatile("cp.async.wait_group 1;" ::: "memory");
        else
            asm volatile("cp.async.wait_group 0;" ::: "memory");
        __syncthreads();
        if (it + 2 < nIter) {
            int stN = st + 2; if (stN >= 3) stN -= 3;
            ISSUE(stN, (it + 2) << 5);
        }

        unsigned aStage = asBase + (unsigned)(st * (AS_WORDS << 2));
        unsigned bStage = bsBase + (unsigned)(st * (BS_WORDS << 2));

        #pragma unroll
        for (int ks = 0; ks < 2; ks++) {
            unsigned a[4][4], bfr[2][4];
            #pragma unroll
            for (int i = 0; i < 4; i++) {
                int row = warpRow * 64 + i * 16 + a_row_l;
                unsigned addr = aStage + (unsigned)((row * 20 + ks * 8 + a_koff) << 2);
                LDSM_X4(a[i], addr);
            }
            #pragma unroll
            for (int j2 = 0; j2 < 2; j2++) {
                int kk = ks * 16 + b_krow;
                int nch = warpCol * 4 + j2 * 2 + b_nchl;
                unsigned addr = bStage + (unsigned)((kk * 64 + ((nch ^ (kk & 7)) * 4)) << 2);
                LDSM_X4T(bfr[j2], addr);
            }
            #pragma unroll
            for (int i = 0; i < 4; i++)
                #pragma unroll
                for (int j = 0; j < 4; j++) {
                    unsigned bb[2] = { bfr[j >> 1][(j & 1) * 2], bfr[j >> 1][(j & 1) * 2 + 1] };
                    mma_fp16(acc[i][j], a[i], bb);
                }
        }
        st++; if (st >= 3) st -= 3;
    }
    #undef ISSUE

    #pragma unroll
    for (int i = 0; i < 4; i++) {
        int r0 = rowBase + warpRow * 64 + i * 16 + gid;
        #pragma unroll
        for (int j = 0; j < 4; j++) {
            int ccj = colBase + warpCol * 32 + j * 8 + tig * 2;
            if (ccj < N) {
                *(float2*)(C + (size_t)r0 * N + ccj)       = make_float2(acc[i][j][0], acc[i][j][1]);
                *(float2*)(C + (size_t)(r0 + 8) * N + ccj) = make_float2(acc[i][j][2], acc[i][j][3]);
            }
        }
    }
}

// ---------------- 3) depthwise causal conv + bias + SiLU (fp16 out only) ----------------
__global__ __launch_bounds__(256) void k_conv(
    const float* __restrict__ cw, const float* __restrict__ cb)
{
    int ch = blockIdx.x * 256 + threadIdx.x;   // 0..2303
    int rb = blockIdx.y * 64;
    int b = rb >> 12;
    int l0 = rb & 4095;
    float w0 = cw[ch], w1 = cw[NCH + ch], w2 = cw[2 * NCH + ch], w3 = cw[3 * NCH + ch];
    float bias = cb[ch];
    const float* src = g_zx + DIN + ch;
    float x1 = 0.f, x2 = 0.f, x3 = 0.f;
    if (l0 >= 1) x1 = src[(size_t)(b * LL + l0 - 1) * NPJ];
    if (l0 >= 2) x2 = src[(size_t)(b * LL + l0 - 2) * NPJ];
    if (l0 >= 3) x3 = src[(size_t)(b * LL + l0 - 3) * NPJ];
    #pragma unroll 4
    for (int i = 0; i < 64; i++) {
        int l = l0 + i;
        float cur = src[(size_t)(b * LL + l) * NPJ];
        float v = siluf(bias + w3 * cur + w2 * x1 + w1 * x2 + w0 * x3);
        g_xBCh[(size_t)(b * LL + l) * NCH + ch] = __float2half(v);
        x3 = x2; x2 = x1; x1 = cur;
    }
}

// ---------------- 4) dt = softplus(raw+bias); per-chunk cumsum of dt*A ----------------
__global__ __launch_bounds__(256) void k_dtscan(
    const float* __restrict__ dtb, const float* __restrict__ alog)
{
    int bc = blockIdx.x, h = blockIdx.y, l = threadIdx.x;
    int b = bc >> 4, c = bc & 15;
    int row = b * LL + c * CHK + l;
    float raw = g_zx[(size_t)row * NPJ + DIN + NCH + h] + dtb[h];
    float dt = softplusf(raw);
    g_dt[row * HH + h] = dt;
    float v = -dt * expf(alog[h]);
    __shared__ float sb[CHK];
    sb[l] = v;
    __syncthreads();
    for (int o = 1; o < CHK; o <<= 1) {
        float add = (l >= o) ? sb[l - o] : 0.f;
        __syncthreads();
        sb[l] += add;
        __syncthreads();
    }
    g_Acum[(bc * HH + h) * CHK + l] = sb[l];
    if (l == CHK - 1) g_cdec[bc * HH + h] = expf(sb[l]);
}

// ---------------- 5) S via MMA: S[s,l] = sum_n B[s,n]*C[l,n] ----------------
// grid (2,2,NBC): 128(s) x 128(l) tile per block; k = 128 n_state, 4 k32 tiles.
// A = B-rows [s][n] stride-40 direct ldsm; B-op = C^T staged [n][l] stride-136 trans ldsm.
__global__ __launch_bounds__(256) void k_S()
{
    int bc = blockIdx.z;
    int b = bc >> 4, c = bc & 15;
    int rowb = b * LL + c * CHK;
    int s0b = blockIdx.x * 128, l0b = blockIdx.y * 128;
    __shared__ __half As[128 * 40];
    __shared__ __half Bt[32 * 136];
    int t = threadIdx.x;
    int lane = t & 31, warp = t >> 5;
    int warpRow = warp >> 2, warpCol = warp & 3;
    int a_row_l = (lane & 7) + ((lane >> 3) & 1) * 8;
    int a_koff  = (lane >> 4) * 8;   // halves
    int b_krow  = ((lane >> 3) & 1) * 8 + (lane & 7);
    int b_nchl  = (lane >> 4);
    int gid = lane >> 2, tig = lane & 3;
    unsigned asB = (unsigned)__cvta_generic_to_shared(As);
    unsigned btB = (unsigned)__cvta_generic_to_shared(Bt);
    const __half2* xbc2 = (const __half2*)g_xBCh;

    float acc[4][4][4] = {};
    for (int kt = 0; kt < 4; kt++) {
        // stage A[s][n] (B rows)
        for (int idx = t; idx < 2048; idx += 256) {
            int n2 = idx & 15, s = idx >> 4;
            __half2 v = xbc2[(size_t)(rowb + s0b + s) * (NCH / 2) + (DIN / 2) + kt * 16 + n2];
            *(__half2*)&As[s * 40 + n2 * 2] = v;
        }
        // stage Bt[n][l] = C[l][n] transpose
        for (int idx = t; idx < 2048; idx += 256) {
            int n2 = idx & 15, l = idx >> 4;
            __half2 v = xbc2[(size_t)(rowb + l0b + l) * (NCH / 2) + (DIN + NSt) / 2 + kt * 16 + n2];
            Bt[(n2 * 2) * 136 + l]     = __low2half(v);
            Bt[(n2 * 2 + 1) * 136 + l] = __high2half(v);
        }
        __syncthreads();
        #pragma unroll
        for (int ks = 0; ks < 2; ks++) {
            unsigned a[4][4], bfr[2][4];
            #pragma unroll
            for (int i = 0; i < 4; i++) {
                int row = warpRow * 64 + i * 16 + a_row_l;
                unsigned addr = asB + (unsigned)((row * 40 + ks * 16 + a_koff) * 2);
                LDSM_X4(a[i], addr);
            }
            #pragma unroll
            for (int j2 = 0; j2 < 2; j2++) {
                int kk = ks * 16 + b_krow;
                int nch = warpCol * 4 + j2 * 2 + b_nchl;
                unsigned addr = btB + (unsigned)((kk * 136 + nch * 8) * 2);
                LDSM_X4T(bfr[j2], addr);
            }
            #pragma unroll
            for (int i = 0; i < 4; i++)
                #pragma unroll
                for (int j = 0; j < 4; j++) {
                    unsigned bb[2] = { bfr[j >> 1][(j & 1) * 2], bfr[j >> 1][(j & 1) * 2 + 1] };
                    mma_fp16(acc[i][j], a[i], bb);
                }
        }
        __syncthreads();
    }
    __half* out = g_S_h + (size_t)bc * CHK * CHK;
    #pragma unroll
    for (int i = 0; i < 4; i++) {
        int r0 = s0b + warpRow * 64 + i * 16 + gid;
        #pragma unroll
        for (int j = 0; j < 4; j++) {
            int col = l0b + warpCol * 32 + j * 8 + tig * 2;
            *(__half2*)&out[(size_t)r0 * CHK + col]       = __floats2half2_rn(acc[i][j][0], acc[i][j][1]);
            *(__half2*)&out[(size_t)(r0 + 8) * CHK + col] = __floats2half2_rn(acc[i][j][2], acc[i][j][3]);
        }
    }
}

// ---------------- 6) states via MMA: states[p,n] = sum_l Xdt[l,p]*Bw[l,n] ----------------
__global__ __launch_bounds__(256) void k_states()
{
    int bc = blockIdx.x, h = blockIdx.y;
    int b = bc >> 4, c = bc & 15;
    int rowb = b * LL + c * CHK;
    const float* Ac = g_Acum + (bc * HH + h) * CHK;
    __shared__ float wsm[32];
    __shared__ __half Xt[64 * 40];     // [p][l] stride 40
    __shared__ __half Bw[32 * 136];    // [l][n] stride 136
    int t = threadIdx.x;
    int lane = t & 31, warp = t >> 5;
    int mb = (warp >> 1) * 16, nb = (warp & 1) * 64;
    int a_row_l = (lane & 7) + ((lane >> 3) & 1) * 8;
    int a_koff  = (lane >> 4) * 8;
    int b_krow  = ((lane >> 3) & 1) * 8 + (lane & 7);
    int b_nchl  = (lane >> 4);
    int gid = lane >> 2, tig = lane & 3;
    unsigned xtB = (unsigned)__cvta_generic_to_shared(Xt);
    unsigned bwB = (unsigned)__cvta_generic_to_shared(Bw);

    float acc[8][4] = {};
    float alast = Ac[CHK - 1];
    const __half2* xbc2 = (const __half2*)g_xBCh;
    for (int lt = 0; lt < 8; lt++) {
        if (t < 32) wsm[t] = __expf(alast - Ac[lt * 32 + t]);
        __syncthreads();
        for (int idx = t; idx < 2048; idx += 256) {
            int n2 = idx & 63, ll = idx >> 6;
            int row = rowb + lt * 32 + ll;
            __half2 v = xbc2[(size_t)row * (NCH / 2) + (DIN / 2) + n2];
            __half2 w = __float2half2_rn(wsm[ll]);
            *(__half2*)&Bw[ll * 136 + n2 * 2] = __hmul2(v, w);
        }
        for (int idx = t; idx < 1024; idx += 256) {
            int p2 = idx & 31, ll = idx >> 5;
            int row = rowb + lt * 32 + ll;
            __half2 v = xbc2[(size_t)row * (NCH / 2) + h * 32 + p2];
            __half2 d = __float2half2_rn(g_dt[row * HH + h]);
            __half2 r = __hmul2(v, d);
            Xt[(p2 * 2) * 40 + ll]     = __low2half(r);
            Xt[(p2 * 2 + 1) * 40 + ll] = __high2half(r);
        }
        __syncthreads();
        #pragma unroll
        for (int ks = 0; ks < 2; ks++) {
            unsigned a[4], bfr[4][4];
            {
                int row = mb + a_row_l;
                unsigned addr = xtB + (unsigned)((row * 40 + ks * 16 + a_koff) * 2);
                LDSM_X4(a, addr);
            }
            #pragma unroll
            for (int j2 = 0; j2 < 4; j2++) {
                int kk = ks * 16 + b_krow;
                int nch = (nb >> 3) + j2 * 2 + b_nchl;
                unsigned addr = bwB + (unsigned)((kk * 136 + nch * 8) * 2);
                LDSM_X4T(bfr[j2], addr);
            }
            #pragma unroll
            for (int j = 0; j < 8; j++) {
                unsigned bb[2] = { bfr[j >> 1][(j & 1) * 2], bfr[j >> 1][(j & 1) * 2 + 1] };
                mma_fp16(acc[j], a, bb);
            }
        }
        __syncthreads();
    }
    float* out = g_states + (size_t)(bc * HH + h) * PP * NSt;
    #pragma unroll
    for (int j = 0; j < 8; j++) {
        int p0 = mb + gid;
        int nn = nb + j * 8 + tig * 2;
        *(float2*)&out[p0 * NSt + nn]       = make_float2(acc[j][0], acc[j][1]);
        *(float2*)&out[(p0 + 8) * NSt + nn] = make_float2(acc[j][2], acc[j][3]);
    }
}

// ---------------- 7) inter-chunk recurrence (fp32 carry, fp16 prev out) ----------------
__global__ __launch_bounds__(256) void k_scan()
{
    int tid = blockIdx.x * 256 + threadIdx.x;  // 524288
    int n = tid & 127;
    int p = (tid >> 7) & 63;
    int h = (tid >> 13) & 31;
    int b = tid >> 18;
    float carry = 0.f;
    for (int c = 0; c < NC; c++) {
        int bc = b * NC + c;
        size_t idx = (size_t)(bc * HH + h) * PP * NSt + p * NSt + n;
        float dec = g_cdec[bc * HH + h];
        g_prev_h[idx] = __float2half(carry);
        carry = carry * dec + g_states[idx];
    }
}

// ---------------- 8) Y = Y_off + Y_diag + D*x via MMA ----------------
__global__ __launch_bounds__(256) void k_Y(const float* __restrict__ Dp)
{
    int bc = blockIdx.x, h = blockIdx.y;
    int b = bc >> 4, c = bc & 15;
    int rowb = b * LL + c * CHK;
    int t = threadIdx.x;
    int lane = t & 31, warp = t >> 5;
    int mb = (warp >> 1) * 64, nb = (warp & 1) * 32;

    __shared__ float Asm[CHK];
    __shared__ float es_all[CHK];      // exp(Acum[s0(s)] - Acum[s]) per s
    __shared__ __half Am[256 * 40];    // Ct (off) / Msm (diag), stride 40
    __shared__ __half Bt[32 * 72];     // Pt (off) / Xs2 (diag), stride 72

    const float* Ac = g_Acum + (bc * HH + h) * CHK;
    Asm[t] = Ac[t];

    int a_row_l = (lane & 7) + ((lane >> 3) & 1) * 8;
    int a_koff  = (lane >> 4) * 8;
    int b_krow  = ((lane >> 3) & 1) * 8 + (lane & 7);
    int b_nchl  = (lane >> 4);
    int gid = lane >> 2, tig = lane & 3;
    unsigned amB = (unsigned)__cvta_generic_to_shared(Am);
    unsigned btB = (unsigned)__cvta_generic_to_shared(Bt);

    float acc[4][4][4] = {};
    const __half2* xbc2 = (const __half2*)g_xBCh;
    const __half* prevp = g_prev_h + (size_t)(bc * HH + h) * PP * NSt;
    __syncthreads();
    // es_all[t] = exp(Acum[tile_base(t)] - Acum[t])  (exponent >= 0, bounded by tile decay)
    es_all[t] = __expf(Asm[t & ~31] - Asm[t]);
    float alv = Asm[t];

    // ---- off phase: k = n_state, 4 tiles of 32 ----
    for (int nt = 0; nt < 4; nt++) {
        for (int idx = t; idx < 4096; idx += 256) {       // Ct[l][kk]
            int kk2 = idx & 15, l = idx >> 4;
            __half2 v = xbc2[(size_t)(rowb + l) * (NCH / 2) + (DIN + NSt) / 2 + nt * 16 + kk2];
            *(__half2*)&Am[l * 40 + kk2 * 2] = v;
        }
        for (int idx = t; idx < 1024; idx += 256) {       // Pt[kk][p] transpose
            int kk2 = idx & 15, p = idx >> 4;
            __half2 v = *(const __half2*)&prevp[p * NSt + nt * 32 + kk2 * 2];
            Bt[(kk2 * 2) * 72 + p]     = __low2half(v);
            Bt[(kk2 * 2 + 1) * 72 + p] = __high2half(v);
        }
        __syncthreads();
        #pragma unroll
        for (int ks = 0; ks < 2; ks++) {
            unsigned a[4][4], bfr[2][4];
            #pragma unroll
            for (int i = 0; i < 4; i++) {
                int row = mb + i * 16 + a_row_l;
                unsigned addr = amB + (unsigned)((row * 40 + ks * 16 + a_koff) * 2);
                LDSM_X4(a[i], addr);
            }
            #pragma unroll
            for (int j2 = 0; j2 < 2; j2++) {
                int kk = ks * 16 + b_krow;
                int nch = (nb >> 3) + j2 * 2 + b_nchl;
                unsigned addr = btB + (unsigned)((kk * 72 + nch * 8) * 2);
                LDSM_X4T(bfr[j2], addr);
            }
            #pragma unroll
            for (int i = 0; i < 4; i++)
                #pragma unroll
                for (int j = 0; j < 4; j++) {
                    unsigned bb[2] = { bfr[j >> 1][(j & 1) * 2], bfr[j >> 1][(j & 1) * 2 + 1] };
                    mma_fp16(acc[i][j], a[i], bb);
                }
        }
        __syncthreads();
    }
    // scale off result by exp(Acum[l])
    #pragma unroll
    for (int i = 0; i < 4; i++) {
        int l0 = mb + i * 16 + gid;
        float e0 = __expf(Asm[l0]);
        float e1 = __expf(Asm[l0 + 8]);
        #pragma unroll
        for (int j = 0; j < 4; j++) {
            acc[i][j][0] *= e0; acc[i][j][1] *= e0;
            acc[i][j][2] *= e1; acc[i][j][3] *= e1;
        }
    }

    // ---- diag phase: k = s, 8 tiles of 32 ----
    const __half* Sp = g_S_h + (size_t)bc * CHK * CHK;
    for (int st8 = 0; st8 < 8; st8++) {
        int s0 = st8 * 32;
        // materialize M[l=t][ss] = S[s][l]*exp(Acum[l]-Acum[s])*(s<=l)
        // exp(Al-As) = exp(Al-As0) * es_all[s], both factors overflow-safe for t>=s0
        if (t >= s0) {
            float el = __expf(alv - Asm[s0]);
            #pragma unroll 4
            for (int ss = 0; ss < 32; ss++) {
                int s = s0 + ss;
                float w = 0.f;
                if (s <= t)
                    w = __half2float(Sp[(size_t)s * CHK + t]) * (el * es_all[s]);
                Am[t * 40 + ss] = __float2half(w);
            }
        } else {
            #pragma unroll 4
            for (int ss = 0; ss < 32; ss++) Am[t * 40 + ss] = __float2half(0.f);
        }
        // stage Xs2[ss][p]
        for (int idx = t; idx < 1024; idx += 256) {
            int p2 = idx & 31, ss = idx >> 5;
            int row = rowb + s0 + ss;
            __half2 v = xbc2[(size_t)row * (NCH / 2) + h * 32 + p2];
            __half2 d = __float2half2_rn(g_dt[row * HH + h]);
            *(__half2*)&Bt[ss * 72 + p2 * 2] = __hmul2(v, d);
        }
        __syncthreads();
        if (mb + 64 > s0) {
            #pragma unroll
            for (int ks = 0; ks < 2; ks++) {
                unsigned a[4][4], bfr[2][4];
                #pragma unroll
                for (int i = 0; i < 4; i++) {
                    int row = mb + i * 16 + a_row_l;
                    unsigned addr = amB + (unsigned)((row * 40 + ks * 16 + a_koff) * 2);
                    LDSM_X4(a[i], addr);
                }
                #pragma unroll
                for (int j2 = 0; j2 < 2; j2++) {
                    int kk = ks * 16 + b_krow;
                    int nch = (nb >> 3) + j2 * 2 + b_nchl;
                    unsigned addr = btB + (unsigned)((kk * 72 + nch * 8) * 2);
                    LDSM_X4T(bfr[j2], addr);
                }
                #pragma unroll
                for (int i = 0; i < 4; i++)
                    #pragma unroll
                    for (int j = 0; j < 4; j++) {
                        unsigned bb[2] = { bfr[j >> 1][(j & 1) * 2], bfr[j >> 1][(j & 1) * 2 + 1] };
                        mma_fp16(acc[i][j], a[i], bb);
                    }
            }
        }
        __syncthreads();
    }

    // ---- skip term (fp16 x) + store fp16 ----
    float dh = Dp[h];
    #pragma unroll
    for (int i = 0; i < 4; i++) {
        int l0 = mb + i * 16 + gid;
        #pragma unroll
        for (int j = 0; j < 4; j++) {
            int p = nb + j * 8 + tig * 2;
            #pragma unroll
            for (int r = 0; r < 2; r++) {
                int row = rowb + l0 + r * 8;
                float2 xv = __half22float2(*(const __half2*)&g_xBCh[(size_t)row * NCH + h * PP + p]);
                *(__half2*)&g_y_h[(size_t)row * DIN + h * PP + p] =
                    __floats2half2_rn(acc[i][j][r * 2 + 0] + dh * xv.x,
                                      acc[i][j][r * 2 + 1] + dh * xv.y);
            }
        }
    }
}

// ---------------- 9) gated SiLU + RMSNorm over 2048 (fp16 in/out) ----------------
__global__ __launch_bounds__(256) void k_gatednorm(const float* __restrict__ gw)
{
    int row = blockIdx.x, t = threadIdx.x;
    size_t yo = (size_t)row * DIN;
    size_t zo = (size_t)row * NPJ;
    float4 vv[2];
    float ssum = 0.f;
    #pragma unroll
    for (int k = 0; k < 2; k++) {
        uint2 u = *(const uint2*)&g_y_h[yo + (size_t)(k * 256 + t) * 4];
        float2 ya = __half22float2(*(__half2*)&u.x), yb = __half22float2(*(__half2*)&u.y);
        float4 zv = ((const float4*)(g_zx + zo))[k * 256 + t];
        float4 v;
        v.x = ya.x * siluf(zv.x); v.y = ya.y * siluf(zv.y);
        v.z = yb.x * siluf(zv.z); v.w = yb.y * siluf(zv.w);
        vv[k] = v;
        ssum += v.x * v.x + v.y * v.y + v.z * v.z + v.w * v.w;
    }
    ssum = blockReduceSum256(ssum);
    float sc = rsqrtf(ssum * (1.0f / DIN) + EPSF);
    __half2* dst = (__half2*)(g_yn_h + yo);
    #pragma unroll
    for (int k = 0; k < 2; k++) {
        float4 w = ((const float4*)gw)[k * 256 + t];
        float4 v = vv[k];
        dst[2 * (k * 256 + t)]     = __floats2half2_rn(v.x * sc * w.x, v.y * sc * w.y);
        dst[2 * (k * 256 + t) + 1] = __floats2half2_rn(v.z * sc * w.z, v.w * sc * w.w);
    }
}

// ---------------- launch ----------------
extern "C" void kernel_launch(void* const* d_in, const int* in_sizes, int n_in,
                              void* d_out, int out_size)
{
    const float* hid  = (const float*)d_in[0];
    const float* resi = (const float*)d_in[1];
    const float* nw   = (const float*)d_in[2];
    const float* inw  = (const float*)d_in[3];
    const float* cw   = (const float*)d_in[4];
    const float* cb   = (const float*)d_in[5];
    const float* dtb  = (const float*)d_in[6];
    const float* alog = (const float*)d_in[7];
    const float* Dp   = (const float*)d_in[8];
    const float* gw   = (const float*)d_in[9];
    const float* ow   = (const float*)d_in[10];

    float* out    = (float*)d_out;
    float* resout = out + (size_t)ROWS * DM;

    float *p_zx;
    __half *p_hn, *p_yn, *p_w1, *p_w2;
    cudaGetSymbolAddress((void**)&p_hn, g_hn_h);
    cudaGetSymbolAddress((void**)&p_zx, g_zx);
    cudaGetSymbolAddress((void**)&p_yn, g_yn_h);
    cudaGetSymbolAddress((void**)&p_w1, g_w1h);
    cudaGetSymbolAddress((void**)&p_w2, g_w2h);

    cudaFuncSetAttribute(gemm_fp16, cudaFuncAttributeMaxDynamicSharedMemorySize, GEMM_SMEM);

    k_round_h<<<(DM * NPJ / 4 + 255) / 256, 256>>>(inw, p_w1, DM * NPJ / 4);
    k_round_h<<<(DIN * DM / 4 + 255) / 256, 256>>>(ow, p_w2, DIN * DM / 4);
    k_addnorm<<<ROWS, 256>>>(hid, resi, nw, resout);
    gemm_fp16<<<dim3((NPJ + 127) / 128, ROWS / 128), 256, GEMM_SMEM>>>(p_hn, p_w1, p_zx, ROWS, NPJ, DM);
    k_conv<<<dim3(NCH / 256, ROWS / 64), 256>>>(cw, cb);
    k_dtscan<<<dim3(NBC, HH), 256>>>(dtb, alog);
    k_S<<<dim3(2, 2, NBC), 256>>>();
    k_states<<<dim3(NBC, HH), 256>>>();
    k_scan<<<(BB * HH * PP * NSt) / 256, 256>>>();
    k_Y<<<dim3(NBC, HH), 256>>>(Dp);
    k_gatednorm<<<ROWS, 256>>>(gw);
    gemm_fp16<<<dim3(DM / 128, ROWS / 128), 256, GEMM_SMEM>>>(p_yn, p_w2, out, ROWS, DM, DIN);
}

// round 15
// speedup vs baseline: 2.5528x; 1.1096x over previous
#include <cuda_runtime.h>
#include <cuda_fp16.h>
#include <math.h>

// ---------------- geometry ----------------
#define BB   2
#define LL   4096
#define DM   1024
#define DIN  2048
#define HH   32
#define PP   64
#define NSt  128
#define NCH  2304      // DIN + 2*NSt
#define NPJ  4384      // 2*DIN + 2*NSt + HH
#define NPJH 2336      // NCH + HH (fp16 half of in_proj output)
#define CHK  256
#define NC   16        // chunks per batch
#define ROWS 8192      // BB*LL
#define NBC  32        // BB*NC
#define EPSF 1e-5f

// ---------------- scratch (static device memory, alloc-free) ----------------
__device__ __half g_hn_h[(size_t)ROWS * DM];     // normalized input (fp16)
__device__ float g_zx[(size_t)ROWS * DIN];       // in_proj z-part (fp32)
__device__ __half g_zxh[(size_t)ROWS * NPJH];    // in_proj xBC+dt part (fp16)
__device__ __half g_xBCh[(size_t)ROWS * NCH];    // conv+silu output fp16 (x | B | C)
__device__ float g_dt[ROWS * HH];                // softplus(dt)
__device__ float g_Acum[NBC * HH * CHK];         // per-chunk inclusive cumsum of dt*A
__device__ float g_cdec[NBC * HH];               // exp(Acum[last]) per (bc,h)
__device__ __half g_S_h[(size_t)NBC * CHK * CHK];// ST[s*256+l] per (b,c), fp16
__device__ float g_states[(size_t)NBC * HH * PP * NSt];
__device__ __half g_prev_h[(size_t)NBC * HH * PP * NSt];
__device__ __half g_y_h[(size_t)ROWS * DIN];     // SSD output (fp16)
__device__ __half g_yn_h[(size_t)ROWS * DIN];    // gated-norm output (fp16)
__device__ __half g_w1h[(size_t)DM * NPJ];       // fp16 in_proj_w
__device__ __half g_w2h[(size_t)DIN * DM];       // fp16 out_proj_w

// ---------------- helpers ----------------
__device__ __forceinline__ float blockReduceSum256(float v) {
    __shared__ float red[32];
    int lane = threadIdx.x & 31, wid = threadIdx.x >> 5;
    #pragma unroll
    for (int o = 16; o; o >>= 1) v += __shfl_down_sync(0xffffffffu, v, o);
    if (lane == 0) red[wid] = v;
    __syncthreads();
    v = (threadIdx.x < 8) ? red[threadIdx.x] : 0.f;
    if (wid == 0) {
        #pragma unroll
        for (int o = 4; o; o >>= 1) v += __shfl_down_sync(0xffffffffu, v, o);
        if (lane == 0) red[0] = v;
    }
    __syncthreads();
    return red[0];
}

__device__ __forceinline__ float softplusf(float x) {
    return (x > 20.f) ? x : log1pf(expf(x));
}
__device__ __forceinline__ float siluf(float x) {
    return x / (1.f + expf(-x));
}
__device__ __forceinline__ void mma_fp16(float* d, const unsigned* a, const unsigned* b) {
    asm volatile(
        "mma.sync.aligned.m16n8k16.row.col.f32.f16.f16.f32 "
        "{%0,%1,%2,%3}, {%4,%5,%6,%7}, {%8,%9}, {%0,%1,%2,%3};"
        : "+f"(d[0]), "+f"(d[1]), "+f"(d[2]), "+f"(d[3])
        : "r"(a[0]), "r"(a[1]), "r"(a[2]), "r"(a[3]), "r"(b[0]), "r"(b[1]));
}
#define LDSM_X4(dst, addr) \
    asm volatile("ldmatrix.sync.aligned.m8n8.x4.shared.b16 {%0,%1,%2,%3}, [%4];" \
        : "=r"((dst)[0]), "=r"((dst)[1]), "=r"((dst)[2]), "=r"((dst)[3]) : "r"(addr))
#define LDSM_X4T(dst, addr) \
    asm volatile("ldmatrix.sync.aligned.m8n8.x4.trans.shared.b16 {%0,%1,%2,%3}, [%4];" \
        : "=r"((dst)[0]), "=r"((dst)[1]), "=r"((dst)[2]), "=r"((dst)[3]) : "r"(addr))

// ---------------- 0) weight pre-convert to fp16 ----------------
__global__ __launch_bounds__(256) void k_round_h(
    const float* __restrict__ in, __half* __restrict__ out, int n4)
{
    int i = blockIdx.x * 256 + threadIdx.x;
    if (i < n4) {
        float4 v = ((const float4*)in)[i];
        ((__half2*)out)[2 * i]     = __floats2half2_rn(v.x, v.y);
        ((__half2*)out)[2 * i + 1] = __floats2half2_rn(v.z, v.w);
    }
}

// ---------------- 1) residual add + RMSNorm (fp16 output) ----------------
__global__ __launch_bounds__(256) void k_addnorm(
    const float* __restrict__ hid, const float* __restrict__ resi,
    const float* __restrict__ w, float* __restrict__ resout)
{
    int row = blockIdx.x, t = threadIdx.x;
    size_t off = (size_t)row * DM;
    float4 hv = ((const float4*)(hid + off))[t];
    float4 rv = ((const float4*)(resi + off))[t];
    hv.x += rv.x; hv.y += rv.y; hv.z += rv.z; hv.w += rv.w;
    ((float4*)(resout + off))[t] = hv;
    float s = hv.x*hv.x + hv.y*hv.y + hv.z*hv.z + hv.w*hv.w;
    s = blockReduceSum256(s);
    float sc = rsqrtf(s * (1.0f / DM) + EPSF);
    float4 wv = ((const float4*)w)[t];
    __half2* dst = (__half2*)(g_hn_h + off);
    dst[2 * t]     = __floats2half2_rn(hv.x * sc * wv.x, hv.y * sc * wv.y);
    dst[2 * t + 1] = __floats2half2_rn(hv.z * sc * wv.z, hv.w * sc * wv.w);
}

// ---------------- 2) FP16 tensor-core GEMM, 3-stage cp.async, split-precision output ----------------
// Columns [0, split) -> fp32 C32 (row stride ldc32); [split, N) -> fp16 C16 (stride ldc16).
#define AS_WORDS (128 * 20)
#define BS_WORDS (32 * 64)
#define GEMM_SMEM (3 * (AS_WORDS + BS_WORDS) * 4)
__global__ __launch_bounds__(256, 2) void gemm_fp16(
    const __half* __restrict__ A, const __half* __restrict__ Bm,
    float* __restrict__ C32, int ldc32, __half* __restrict__ C16, int ldc16,
    int split, int M, int N, int K)
{
    extern __shared__ unsigned smemBuf[];
    unsigned* AsBase = smemBuf;
    unsigned* BsBase = smemBuf + 3 * AS_WORDS;

    int tid = threadIdx.x;
    int lane = tid & 31, warp = tid >> 5;
    int warpRow = warp >> 2, warpCol = warp & 3;
    int rowBase = blockIdx.y * 128, colBase = blockIdx.x * 128;

    int aRow = tid >> 2, aChunk = (tid & 3);
    int bk = tid >> 4, bc = tid & 15;
    int gid = lane >> 2, tig = lane & 3;

    unsigned asBase = (unsigned)__cvta_generic_to_shared(AsBase);
    unsigned bsBase = (unsigned)__cvta_generic_to_shared(BsBase);

    const __half* aPtr0 = A + (size_t)(rowBase + aRow) * K + aChunk * 8;
    const __half* aPtr1 = A + (size_t)(rowBase + aRow + 64) * K + aChunk * 8;
    int cc = colBase + bc * 8;
    const __half* bPtr0 = Bm + (size_t)bk * N + cc;
    const __half* bPtr1 = Bm + (size_t)(bk + 16) * N + cc;
    int bsz = (cc < N) ? 16 : 0;

    unsigned da0 = asBase + (unsigned)((aRow * 20 + aChunk * 4) << 2);
    unsigned da1 = da0 + (64 * 20 << 2);
    unsigned db0 = bsBase + (unsigned)((bk * 64 + ((bc ^ (bk & 7)) * 4)) << 2);
    unsigned db1 = db0 + (16 * 64 << 2);

    int nIter = K >> 5;

    #define ISSUE(st, k0) do {                                                        \
        unsigned aoff = (unsigned)(st) * (AS_WORDS << 2);                             \
        unsigned boff = (unsigned)(st) * (BS_WORDS << 2);                             \
        asm volatile("cp.async.cg.shared.global [%0], [%1], 16;"                      \
                     :: "r"(da0 + aoff), "l"(aPtr0 + (k0)) : "memory");               \
        asm volatile("cp.async.cg.shared.global [%0], [%1], 16;"                      \
                     :: "r"(da1 + aoff), "l"(aPtr1 + (k0)) : "memory");               \
        asm volatile("cp.async.cg.shared.global [%0], [%1], 16, %2;"                  \
                     :: "r"(db0 + boff), "l"(bPtr0 + (size_t)(k0) * N), "r"(bsz) : "memory"); \
        asm volatile("cp.async.cg.shared.global [%0], [%1], 16, %2;"                  \
                     :: "r"(db1 + boff), "l"(bPtr1 + (size_t)(k0) * N), "r"(bsz) : "memory"); \
        asm volatile("cp.async.commit_group;" ::: "memory");                          \
    } while (0)

    float acc[4][4][4] = {};

    ISSUE(0, 0);
    if (nIter > 1) ISSUE(1, 32);

    int a_row_l = (lane & 7) + ((lane >> 3) & 1) * 8;
    int a_koff  = (lane >> 4) * 4;
    int b_krow  = ((lane >> 3) & 1) * 8 + (lane & 7);
    int b_nchl  = (lane >> 4);

    int st = 0;
    for (int it = 0; it < nIter; it++) {
        if (it + 1 < nIter)
            asm volatile("cp.async.wait_group 1;" ::: "memory");
        else
            asm volatile("cp.async.wait_group 0;" ::: "memory");
        __syncthreads();
        if (it + 2 < nIter) {
            int stN = st + 2; if (stN >= 3) stN -= 3;
            ISSUE(stN, (it + 2) << 5);
        }

        unsigned aStage = asBase + (unsigned)(st * (AS_WORDS << 2));
        unsigned bStage = bsBase + (unsigned)(st * (BS_WORDS << 2));

        #pragma unroll
        for (int ks = 0; ks < 2; ks++) {
            unsigned a[4][4], bfr[2][4];
            #pragma unroll
            for (int i = 0; i < 4; i++) {
                int row = warpRow * 64 + i * 16 + a_row_l;
                unsigned addr = aStage + (unsigned)((row * 20 + ks * 8 + a_koff) << 2);
                LDSM_X4(a[i], addr);
            }
            #pragma unroll
            for (int j2 = 0; j2 < 2; j2++) {
                int kk = ks * 16 + b_krow;
                int nch = warpCol * 4 + j2 * 2 + b_nchl;
                unsigned addr = bStage + (unsigned)((kk * 64 + ((nch ^ (kk & 7)) * 4)) << 2);
                LDSM_X4T(bfr[j2], addr);
            }
            #pragma unroll
            for (int i = 0; i < 4; i++)
                #pragma unroll
                for (int j = 0; j < 4; j++) {
                    unsigned bb[2] = { bfr[j >> 1][(j & 1) * 2], bfr[j >> 1][(j & 1) * 2 + 1] };
                    mma_fp16(acc[i][j], a[i], bb);
                }
        }
        st++; if (st >= 3) st -= 3;
    }
    #undef ISSUE

    #pragma unroll
    for (int i = 0; i < 4; i++) {
        int r0 = rowBase + warpRow * 64 + i * 16 + gid;
        #pragma unroll
        for (int j = 0; j < 4; j++) {
            int ccj = colBase + warpCol * 32 + j * 8 + tig * 2;
            if (ccj < N) {
                if (ccj < split) {
                    *(float2*)(C32 + (size_t)r0 * ldc32 + ccj)       = make_float2(acc[i][j][0], acc[i][j][1]);
                    *(float2*)(C32 + (size_t)(r0 + 8) * ldc32 + ccj) = make_float2(acc[i][j][2], acc[i][j][3]);
                } else {
                    int ch = ccj - split;
                    *(__half2*)(C16 + (size_t)r0 * ldc16 + ch)       = __floats2half2_rn(acc[i][j][0], acc[i][j][1]);
                    *(__half2*)(C16 + (size_t)(r0 + 8) * ldc16 + ch) = __floats2half2_rn(acc[i][j][2], acc[i][j][3]);
                }
            }
        }
    }
}

// ---------------- 3) depthwise causal conv + bias + SiLU (fp16 in/out) ----------------
__global__ __launch_bounds__(256) void k_conv(
    const float* __restrict__ cw, const float* __restrict__ cb)
{
    int ch = blockIdx.x * 256 + threadIdx.x;   // 0..2303
    int rb = blockIdx.y * 64;
    int b = rb >> 12;
    int l0 = rb & 4095;
    float w0 = cw[ch], w1 = cw[NCH + ch], w2 = cw[2 * NCH + ch], w3 = cw[3 * NCH + ch];
    float bias = cb[ch];
    const __half* src = g_zxh + ch;
    float x1 = 0.f, x2 = 0.f, x3 = 0.f;
    if (l0 >= 1) x1 = __half2float(src[(size_t)(b * LL + l0 - 1) * NPJH]);
    if (l0 >= 2) x2 = __half2float(src[(size_t)(b * LL + l0 - 2) * NPJH]);
    if (l0 >= 3) x3 = __half2float(src[(size_t)(b * LL + l0 - 3) * NPJH]);
    #pragma unroll 4
    for (int i = 0; i < 64; i++) {
        int l = l0 + i;
        float cur = __half2float(src[(size_t)(b * LL + l) * NPJH]);
        float v = siluf(bias + w3 * cur + w2 * x1 + w1 * x2 + w0 * x3);
        g_xBCh[(size_t)(b * LL + l) * NCH + ch] = __float2half(v);
        x3 = x2; x2 = x1; x1 = cur;
    }
}

// ---------------- 4) dt = softplus(raw+bias); per-chunk cumsum of dt*A ----------------
__global__ __launch_bounds__(256) void k_dtscan(
    const float* __restrict__ dtb, const float* __restrict__ alog)
{
    int bc = blockIdx.x, h = blockIdx.y, l = threadIdx.x;
    int b = bc >> 4, c = bc & 15;
    int row = b * LL + c * CHK + l;
    float raw = __half2float(g_zxh[(size_t)row * NPJH + NCH + h]) + dtb[h];
    float dt = softplusf(raw);
    g_dt[row * HH + h] = dt;
    float v = -dt * expf(alog[h]);
    __shared__ float sb[CHK];
    sb[l] = v;
    __syncthreads();
    for (int o = 1; o < CHK; o <<= 1) {
        float add = (l >= o) ? sb[l - o] : 0.f;
        __syncthreads();
        sb[l] += add;
        __syncthreads();
    }
    g_Acum[(bc * HH + h) * CHK + l] = sb[l];
    if (l == CHK - 1) g_cdec[bc * HH + h] = expf(sb[l]);
}

// ---------------- 5) S via MMA: S[s,l] = sum_n B[s,n]*C[l,n] ----------------
__global__ __launch_bounds__(256) void k_S()
{
    int bc = blockIdx.z;
    int b = bc >> 4, c = bc & 15;
    int rowb = b * LL + c * CHK;
    int s0b = blockIdx.x * 128, l0b = blockIdx.y * 128;
    __shared__ __half As[128 * 40];
    __shared__ __half Bt[32 * 136];
    int t = threadIdx.x;
    int lane = t & 31, warp = t >> 5;
    int warpRow = warp >> 2, warpCol = warp & 3;
    int a_row_l = (lane & 7) + ((lane >> 3) & 1) * 8;
    int a_koff  = (lane >> 4) * 8;   // halves
    int b_krow  = ((lane >> 3) & 1) * 8 + (lane & 7);
    int b_nchl  = (lane >> 4);
    int gid = lane >> 2, tig = lane & 3;
    unsigned asB = (unsigned)__cvta_generic_to_shared(As);
    unsigned btB = (unsigned)__cvta_generic_to_shared(Bt);
    const __half2* xbc2 = (const __half2*)g_xBCh;

    float acc[4][4][4] = {};
    for (int kt = 0; kt < 4; kt++) {
        for (int idx = t; idx < 2048; idx += 256) {
            int n2 = idx & 15, s = idx >> 4;
            __half2 v = xbc2[(size_t)(rowb + s0b + s) * (NCH / 2) + (DIN / 2) + kt * 16 + n2];
            *(__half2*)&As[s * 40 + n2 * 2] = v;
        }
        for (int idx = t; idx < 2048; idx += 256) {
            int n2 = idx & 15, l = idx >> 4;
            __half2 v = xbc2[(size_t)(rowb + l0b + l) * (NCH / 2) + (DIN + NSt) / 2 + kt * 16 + n2];
            Bt[(n2 * 2) * 136 + l]     = __low2half(v);
            Bt[(n2 * 2 + 1) * 136 + l] = __high2half(v);
        }
        __syncthreads();
        #pragma unroll
        for (int ks = 0; ks < 2; ks++) {
            unsigned a[4][4], bfr[2][4];
            #pragma unroll
            for (int i = 0; i < 4; i++) {
                int row = warpRow * 64 + i * 16 + a_row_l;
                unsigned addr = asB + (unsigned)((row * 40 + ks * 16 + a_koff) * 2);
                LDSM_X4(a[i], addr);
            }
            #pragma unroll
            for (int j2 = 0; j2 < 2; j2++) {
                int kk = ks * 16 + b_krow;
                int nch = warpCol * 4 + j2 * 2 + b_nchl;
                unsigned addr = btB + (unsigned)((kk * 136 + nch * 8) * 2);
                LDSM_X4T(bfr[j2], addr);
            }
            #pragma unroll
            for (int i = 0; i < 4; i++)
                #pragma unroll
                for (int j = 0; j < 4; j++) {
                    unsigned bb[2] = { bfr[j >> 1][(j & 1) * 2], bfr[j >> 1][(j & 1) * 2 + 1] };
                    mma_fp16(acc[i][j], a[i], bb);
                }
        }
        __syncthreads();
    }
    __half* out = g_S_h + (size_t)bc * CHK * CHK;
    #pragma unroll
    for (int i = 0; i < 4; i++) {
        int r0 = s0b + warpRow * 64 + i * 16 + gid;
        #pragma unroll
        for (int j = 0; j < 4; j++) {
            int col = l0b + warpCol * 32 + j * 8 + tig * 2;
            *(__half2*)&out[(size_t)r0 * CHK + col]       = __floats2half2_rn(acc[i][j][0], acc[i][j][1]);
            *(__half2*)&out[(size_t)(r0 + 8) * CHK + col] = __floats2half2_rn(acc[i][j][2], acc[i][j][3]);
        }
    }
}

// ---------------- 6) states via MMA: states[p,n] = sum_l Xdt[l,p]*Bw[l,n] ----------------
__global__ __launch_bounds__(256) void k_states()
{
    int bc = blockIdx.x, h = blockIdx.y;
    int b = bc >> 4, c = bc & 15;
    int rowb = b * LL + c * CHK;
    const float* Ac = g_Acum + (bc * HH + h) * CHK;
    __shared__ float wsm[32];
    __shared__ __half Xt[64 * 40];
    __shared__ __half Bw[32 * 136];
    int t = threadIdx.x;
    int lane = t & 31, warp = t >> 5;
    int mb = (warp >> 1) * 16, nb = (warp & 1) * 64;
    int a_row_l = (lane & 7) + ((lane >> 3) & 1) * 8;
    int a_koff  = (lane >> 4) * 8;
    int b_krow  = ((lane >> 3) & 1) * 8 + (lane & 7);
    int b_nchl  = (lane >> 4);
    int gid = lane >> 2, tig = lane & 3;
    unsigned xtB = (unsigned)__cvta_generic_to_shared(Xt);
    unsigned bwB = (unsigned)__cvta_generic_to_shared(Bw);

    float acc[8][4] = {};
    float alast = Ac[CHK - 1];
    const __half2* xbc2 = (const __half2*)g_xBCh;
    for (int lt = 0; lt < 8; lt++) {
        if (t < 32) wsm[t] = __expf(alast - Ac[lt * 32 + t]);
        __syncthreads();
        for (int idx = t; idx < 2048; idx += 256) {
            int n2 = idx & 63, ll = idx >> 6;
            int row = rowb + lt * 32 + ll;
            __half2 v = xbc2[(size_t)row * (NCH / 2) + (DIN / 2) + n2];
            __half2 w = __float2half2_rn(wsm[ll]);
            *(__half2*)&Bw[ll * 136 + n2 * 2] = __hmul2(v, w);
        }
        for (int idx = t; idx < 1024; idx += 256) {
            int p2 = idx & 31, ll = idx >> 5;
            int row = rowb + lt * 32 + ll;
            __half2 v = xbc2[(size_t)row * (NCH / 2) + h * 32 + p2];
            __half2 d = __float2half2_rn(g_dt[row * HH + h]);
            __half2 r = __hmul2(v, d);
            Xt[(p2 * 2) * 40 + ll]     = __low2half(r);
            Xt[(p2 * 2 + 1) * 40 + ll] = __high2half(r);
        }
        __syncthreads();
        #pragma unroll
        for (int ks = 0; ks < 2; ks++) {
            unsigned a[4], bfr[4][4];
            {
                int row = mb + a_row_l;
                unsigned addr = xtB + (unsigned)((row * 40 + ks * 16 + a_koff) * 2);
                LDSM_X4(a, addr);
            }
            #pragma unroll
            for (int j2 = 0; j2 < 4; j2++) {
                int kk = ks * 16 + b_krow;
                int nch = (nb >> 3) + j2 * 2 + b_nchl;
                unsigned addr = bwB + (unsigned)((kk * 136 + nch * 8) * 2);
                LDSM_X4T(bfr[j2], addr);
            }
            #pragma unroll
            for (int j = 0; j < 8; j++) {
                unsigned bb[2] = { bfr[j >> 1][(j & 1) * 2], bfr[j >> 1][(j & 1) * 2 + 1] };
                mma_fp16(acc[j], a, bb);
            }
        }
        __syncthreads();
    }
    float* out = g_states + (size_t)(bc * HH + h) * PP * NSt;
    #pragma unroll
    for (int j = 0; j < 8; j++) {
        int p0 = mb + gid;
        int nn = nb + j * 8 + tig * 2;
        *(float2*)&out[p0 * NSt + nn]       = make_float2(acc[j][0], acc[j][1]);
        *(float2*)&out[(p0 + 8) * NSt + nn] = make_float2(acc[j][2], acc[j][3]);
    }
}

// ---------------- 7) inter-chunk recurrence (fp32 carry, fp16 prev out) ----------------
__global__ __launch_bounds__(256) void k_scan()
{
    int tid = blockIdx.x * 256 + threadIdx.x;  // 524288
    int n = tid & 127;
    int p = (tid >> 7) & 63;
    int h = (tid >> 13) & 31;
    int b = tid >> 18;
    float carry = 0.f;
    for (int c = 0; c < NC; c++) {
        int bc = b * NC + c;
        size_t idx = (size_t)(bc * HH + h) * PP * NSt + p * NSt + n;
        float dec = g_cdec[bc * HH + h];
        g_prev_h[idx] = __float2half(carry);
        carry = carry * dec + g_states[idx];
    }
}

// ---------------- 8) Y = Y_off + Y_diag + D*x via MMA ----------------
__global__ __launch_bounds__(256) void k_Y(const float* __restrict__ Dp)
{
    int bc = blockIdx.x, h = blockIdx.y;
    int b = bc >> 4, c = bc & 15;
    int rowb = b * LL + c * CHK;
    int t = threadIdx.x;
    int lane = t & 31, warp = t >> 5;
    int mb = (warp >> 1) * 64, nb = (warp & 1) * 32;

    __shared__ float Asm[CHK];
    __shared__ float es_all[CHK];
    __shared__ __half Am[256 * 40];
    __shared__ __half Bt[32 * 72];

    const float* Ac = g_Acum + (bc * HH + h) * CHK;
    Asm[t] = Ac[t];

    int a_row_l = (lane & 7) + ((lane >> 3) & 1) * 8;
    int a_koff  = (lane >> 4) * 8;
    int b_krow  = ((lane >> 3) & 1) * 8 + (lane & 7);
    int b_nchl  = (lane >> 4);
    int gid = lane >> 2, tig = lane & 3;
    unsigned amB = (unsigned)__cvta_generic_to_shared(Am);
    unsigned btB = (unsigned)__cvta_generic_to_shared(Bt);

    float acc[4][4][4] = {};
    const __half2* xbc2 = (const __half2*)g_xBCh;
    const __half* prevp = g_prev_h + (size_t)(bc * HH + h) * PP * NSt;
    __syncthreads();
    es_all[t] = __expf(Asm[t & ~31] - Asm[t]);
    float alv = Asm[t];

    // ---- off phase: k = n_state, 4 tiles of 32 ----
    for (int nt = 0; nt < 4; nt++) {
        for (int idx = t; idx < 4096; idx += 256) {
            int kk2 = idx & 15, l = idx >> 4;
            __half2 v = xbc2[(size_t)(rowb + l) * (NCH / 2) + (DIN + NSt) / 2 + nt * 16 + kk2];
            *(__half2*)&Am[l * 40 + kk2 * 2] = v;
        }
        for (int idx = t; idx < 1024; idx += 256) {
            int kk2 = idx & 15, p = idx >> 4;
            __half2 v = *(const __half2*)&prevp[p * NSt + nt * 32 + kk2 * 2];
            Bt[(kk2 * 2) * 72 + p]     = __low2half(v);
            Bt[(kk2 * 2 + 1) * 72 + p] = __high2half(v);
        }
        __syncthreads();
        #pragma unroll
        for (int ks = 0; ks < 2; ks++) {
            unsigned a[4][4], bfr[2][4];
            #pragma unroll
            for (int i = 0; i < 4; i++) {
                int row = mb + i * 16 + a_row_l;
                unsigned addr = amB + (unsigned)((row * 40 + ks * 16 + a_koff) * 2);
                LDSM_X4(a[i], addr);
            }
            #pragma unroll
            for (int j2 = 0; j2 < 2; j2++) {
                int kk = ks * 16 + b_krow;
                int nch = (nb >> 3) + j2 * 2 + b_nchl;
                unsigned addr = btB + (unsigned)((kk * 72 + nch * 8) * 2);
                LDSM_X4T(bfr[j2], addr);
            }
            #pragma unroll
            for (int i = 0; i < 4; i++)
                #pragma unroll
                for (int j = 0; j < 4; j++) {
                    unsigned bb[2] = { bfr[j >> 1][(j & 1) * 2], bfr[j >> 1][(j & 1) * 2 + 1] };
                    mma_fp16(acc[i][j], a[i], bb);
                }
        }
        __syncthreads();
    }
    #pragma unroll
    for (int i = 0; i < 4; i++) {
        int l0 = mb + i * 16 + gid;
        float e0 = __expf(Asm[l0]);
        float e1 = __expf(Asm[l0 + 8]);
        #pragma unroll
        for (int j = 0; j < 4; j++) {
            acc[i][j][0] *= e0; acc[i][j][1] *= e0;
            acc[i][j][2] *= e1; acc[i][j][3] *= e1;
        }
    }

    // ---- diag phase: k = s, 8 tiles of 32 ----
    const __half* Sp = g_S_h + (size_t)bc * CHK * CHK;
    for (int st8 = 0; st8 < 8; st8++) {
        int s0 = st8 * 32;
        // materialize M[l=t][ss] = S[s][l]*exp(Acum[l]-Acum[s])*(s<=l), uint4 stores
        if (t >= s0) {
            float el = __expf(alv - Asm[s0]);
            #pragma unroll
            for (int g4 = 0; g4 < 4; g4++) {
                float w[8];
                #pragma unroll
                for (int k = 0; k < 8; k++) {
                    int s = s0 + g4 * 8 + k;
                    w[k] = (s <= t) ? __half2float(Sp[(size_t)s * CHK + t]) * (el * es_all[s]) : 0.f;
                }
                uint4 u;
                *(__half2*)&u.x = __floats2half2_rn(w[0], w[1]);
                *(__half2*)&u.y = __floats2half2_rn(w[2], w[3]);
                *(__half2*)&u.z = __floats2half2_rn(w[4], w[5]);
                *(__half2*)&u.w = __floats2half2_rn(w[6], w[7]);
                *(uint4*)&Am[t * 40 + g4 * 8] = u;
            }
        } else {
            uint4 z = make_uint4(0, 0, 0, 0);
            #pragma unroll
            for (int g4 = 0; g4 < 4; g4++) *(uint4*)&Am[t * 40 + g4 * 8] = z;
        }
        // stage Xs2[ss][p]
        for (int idx = t; idx < 1024; idx += 256) {
            int p2 = idx & 31, ss = idx >> 5;
            int row = rowb + s0 + ss;
            __half2 v = xbc2[(size_t)row * (NCH / 2) + h * 32 + p2];
            __half2 d = __float2half2_rn(g_dt[row * HH + h]);
            *(__half2*)&Bt[ss * 72 + p2 * 2] = __hmul2(v, d);
        }
        __syncthreads();
        if (mb + 64 > s0) {
            #pragma unroll
            for (int ks = 0; ks < 2; ks++) {
                unsigned a[4][4], bfr[2][4];
                #pragma unroll
                for (int i = 0; i < 4; i++) {
                    int row = mb + i * 16 + a_row_l;
                    unsigned addr = amB + (unsigned)((row * 40 + ks * 16 + a_koff) * 2);
                    LDSM_X4(a[i], addr);
                }
                #pragma unroll
                for (int j2 = 0; j2 < 2; j2++) {
                    int kk = ks * 16 + b_krow;
                    int nch = (nb >> 3) + j2 * 2 + b_nchl;
                    unsigned addr = btB + (unsigned)((kk * 72 + nch * 8) * 2);
                    LDSM_X4T(bfr[j2], addr);
                }
                #pragma unroll
                for (int i = 0; i < 4; i++)
                    #pragma unroll
                    for (int j = 0; j < 4; j++) {
                        unsigned bb[2] = { bfr[j >> 1][(j & 1) * 2], bfr[j >> 1][(j & 1) * 2 + 1] };
                        mma_fp16(acc[i][j], a[i], bb);
                    }
            }
        }
        __syncthreads();
    }

    // ---- skip term (fp16 x) + store fp16 ----
    float dh = Dp[h];
    #pragma unroll
    for (int i = 0; i < 4; i++) {
        int l0 = mb + i * 16 + gid;
        #pragma unroll
        for (int j = 0; j < 4; j++) {
            int p = nb + j * 8 + tig * 2;
            #pragma unroll
            for (int r = 0; r < 2; r++) {
                int row = rowb + l0 + r * 8;
                float2 xv = __half22float2(*(const __half2*)&g_xBCh[(size_t)row * NCH + h * PP + p]);
                *(__half2*)&g_y_h[(size_t)row * DIN + h * PP + p] =
                    __floats2half2_rn(acc[i][j][r * 2 + 0] + dh * xv.x,
                                      acc[i][j][r * 2 + 1] + dh * xv.y);
            }
        }
    }
}

// ---------------- 9) gated SiLU + RMSNorm over 2048 (fp16 in/out) ----------------
__global__ __launch_bounds__(256) void k_gatednorm(const float* __restrict__ gw)
{
    int row = blockIdx.x, t = threadIdx.x;
    size_t yo = (size_t)row * DIN;
    float4 vv[2];
    float ssum = 0.f;
    #pragma unroll
    for (int k = 0; k < 2; k++) {
        uint2 u = *(const uint2*)&g_y_h[yo + (size_t)(k * 256 + t) * 4];
        float2 ya = __half22float2(*(__half2*)&u.x), yb = __half22float2(*(__half2*)&u.y);
        float4 zv = ((const float4*)(g_zx + yo))[k * 256 + t];
        float4 v;
        v.x = ya.x * siluf(zv.x); v.y = ya.y * siluf(zv.y);
        v.z = yb.x * siluf(zv.z); v.w = yb.y * siluf(zv.w);
        vv[k] = v;
        ssum += v.x * v.x + v.y * v.y + v.z * v.z + v.w * v.w;
    }
    ssum = blockReduceSum256(ssum);
    float sc = rsqrtf(ssum * (1.0f / DIN) + EPSF);
    __half2* dst = (__half2*)(g_yn_h + yo);
    #pragma unroll
    for (int k = 0; k < 2; k++) {
        float4 w = ((const float4*)gw)[k * 256 + t];
        float4 v = vv[k];
        dst[2 * (k * 256 + t)]     = __floats2half2_rn(v.x * sc * w.x, v.y * sc * w.y);
        dst[2 * (k * 256 + t) + 1] = __floats2half2_rn(v.z * sc * w.z, v.w * sc * w.w);
    }
}

// ---------------- launch ----------------
extern "C" void kernel_launch(void* const* d_in, const int* in_sizes, int n_in,
                              void* d_out, int out_size)
{
    const float* hid  = (const float*)d_in[0];
    const float* resi = (const float*)d_in[1];
    const float* nw   = (const float*)d_in[2];
    const float* inw  = (const float*)d_in[3];
    const float* cw   = (const float*)d_in[4];
    const float* cb   = (const float*)d_in[5];
    const float* dtb  = (const float*)d_in[6];
    const float* alog = (const float*)d_in[7];
    const float* Dp   = (const float*)d_in[8];
    const float* gw   = (const float*)d_in[9];
    const float* ow   = (const float*)d_in[10];

    float* out    = (float*)d_out;
    float* resout = out + (size_t)ROWS * DM;

    float *p_zx;
    __half *p_hn, *p_zxh, *p_yn, *p_w1, *p_w2;
    cudaGetSymbolAddress((void**)&p_hn, g_hn_h);
    cudaGetSymbolAddress((void**)&p_zx, g_zx);
    cudaGetSymbolAddress((void**)&p_zxh, g_zxh);
    cudaGetSymbolAddress((void**)&p_yn, g_yn_h);
    cudaGetSymbolAddress((void**)&p_w1, g_w1h);
    cudaGetSymbolAddress((void**)&p_w2, g_w2h);

    cudaFuncSetAttribute(gemm_fp16, cudaFuncAttributeMaxDynamicSharedMemorySize, GEMM_SMEM);

    k_round_h<<<(DM * NPJ / 4 + 255) / 256, 256>>>(inw, p_w1, DM * NPJ / 4);
    k_round_h<<<(DIN * DM / 4 + 255) / 256, 256>>>(ow, p_w2, DIN * DM / 4);
    k_addnorm<<<ROWS, 256>>>(hid, resi, nw, resout);
    gemm_fp16<<<dim3((NPJ + 127) / 128, ROWS / 128), 256, GEMM_SMEM>>>(
        p_hn, p_w1, p_zx, DIN, p_zxh, NPJH, DIN, ROWS, NPJ, DM);
    k_conv<<<dim3(NCH / 256, ROWS / 64), 256>>>(cw, cb);
    k_dtscan<<<dim3(NBC, HH), 256>>>(dtb, alog);
    k_S<<<dim3(2, 2, NBC), 256>>>();
    k_states<<<dim3(NBC, HH), 256>>>();
    k_scan<<<(BB * HH * PP * NSt) / 256, 256>>>();
    k_Y<<<dim3(NBC, HH), 256>>>(Dp);
    k_gatednorm<<<ROWS, 256>>>(gw);
    gemm_fp16<<<dim3(DM / 128, ROWS / 128), 256, GEMM_SMEM>>>(
        p_yn, p_w2, out, DM, p_zxh, 1, DM, ROWS, DM, DIN);
}

// round 16
// speedup vs baseline: 2.5798x; 1.0106x over previous
#include <cuda_runtime.h>
#include <cuda_fp16.h>
#include <math.h>

// ---------------- geometry ----------------
#define BB   2
#define LL   4096
#define DM   1024
#define DIN  2048
#define HH   32
#define PP   64
#define NSt  128
#define NCH  2304      // DIN + 2*NSt
#define NPJ  4384      // 2*DIN + 2*NSt + HH
#define NPJH 2336      // NCH + HH (fp16 half of in_proj output)
#define CHK  256
#define NC   16        // chunks per batch
#define ROWS 8192      // BB*LL
#define NBC  32        // BB*NC
#define EPSF 1e-5f

// ---------------- scratch (static device memory, alloc-free) ----------------
__device__ __half g_hn_h[(size_t)ROWS * DM];     // normalized input (fp16)
__device__ float g_zx[(size_t)ROWS * DIN];       // in_proj z-part (fp32)
__device__ __half g_zxh[(size_t)ROWS * NPJH];    // in_proj xBC+dt part (fp16)
__device__ __half g_xBCh[(size_t)ROWS * NCH];    // conv+silu output fp16 (x | B | C)
__device__ float g_dt[ROWS * HH];                // softplus(dt)
__device__ float g_Acum[NBC * HH * CHK];         // per-chunk inclusive cumsum of dt*A
__device__ float g_cdec[NBC * HH];               // exp(Acum[last]) per (bc,h)
__device__ __half g_S_h[(size_t)NBC * CHK * CHK];// ST[s*256+l] per (b,c), fp16
__device__ float g_states[(size_t)NBC * HH * PP * NSt];
__device__ __half g_prev_h[(size_t)NBC * HH * PP * NSt];
__device__ __half g_y_h[(size_t)ROWS * DIN];     // SSD output (fp16)
__device__ __half g_yn_h[(size_t)ROWS * DIN];    // gated-norm output (fp16)
__device__ __half g_w1h[(size_t)DM * NPJ];       // fp16 in_proj_w
__device__ __half g_w2h[(size_t)DIN * DM];       // fp16 out_proj_w

// ---------------- helpers ----------------
__device__ __forceinline__ float blockReduceSum256(float v) {
    __shared__ float red[32];
    int lane = threadIdx.x & 31, wid = threadIdx.x >> 5;
    #pragma unroll
    for (int o = 16; o; o >>= 1) v += __shfl_down_sync(0xffffffffu, v, o);
    if (lane == 0) red[wid] = v;
    __syncthreads();
    v = (threadIdx.x < 8) ? red[threadIdx.x] : 0.f;
    if (wid == 0) {
        #pragma unroll
        for (int o = 4; o; o >>= 1) v += __shfl_down_sync(0xffffffffu, v, o);
        if (lane == 0) red[0] = v;
    }
    __syncthreads();
    return red[0];
}

__device__ __forceinline__ float softplusf(float x) {
    return (x > 20.f) ? x : log1pf(expf(x));
}
__device__ __forceinline__ float siluf(float x) {
    return x / (1.f + expf(-x));
}
__device__ __forceinline__ void mma_fp16(float* d, const unsigned* a, const unsigned* b) {
    asm volatile(
        "mma.sync.aligned.m16n8k16.row.col.f32.f16.f16.f32 "
        "{%0,%1,%2,%3}, {%4,%5,%6,%7}, {%8,%9}, {%0,%1,%2,%3};"
        : "+f"(d[0]), "+f"(d[1]), "+f"(d[2]), "+f"(d[3])
        : "r"(a[0]), "r"(a[1]), "r"(a[2]), "r"(a[3]), "r"(b[0]), "r"(b[1]));
}
#define LDSM_X4(dst, addr) \
    asm volatile("ldmatrix.sync.aligned.m8n8.x4.shared.b16 {%0,%1,%2,%3}, [%4];" \
        : "=r"((dst)[0]), "=r"((dst)[1]), "=r"((dst)[2]), "=r"((dst)[3]) : "r"(addr))
#define LDSM_X4T(dst, addr) \
    asm volatile("ldmatrix.sync.aligned.m8n8.x4.trans.shared.b16 {%0,%1,%2,%3}, [%4];" \
        : "=r"((dst)[0]), "=r"((dst)[1]), "=r"((dst)[2]), "=r"((dst)[3]) : "r"(addr))

// ---------------- 0) weight pre-convert to fp16 ----------------
__global__ __launch_bounds__(256) void k_round_h(
    const float* __restrict__ in, __half* __restrict__ out, int n4)
{
    int i = blockIdx.x * 256 + threadIdx.x;
    if (i < n4) {
        float4 v = ((const float4*)in)[i];
        ((__half2*)out)[2 * i]     = __floats2half2_rn(v.x, v.y);
        ((__half2*)out)[2 * i + 1] = __floats2half2_rn(v.z, v.w);
    }
}

// ---------------- 1) residual add + RMSNorm (fp16 output) ----------------
__global__ __launch_bounds__(256) void k_addnorm(
    const float* __restrict__ hid, const float* __restrict__ resi,
    const float* __restrict__ w, float* __restrict__ resout)
{
    int row = blockIdx.x, t = threadIdx.x;
    size_t off = (size_t)row * DM;
    float4 hv = ((const float4*)(hid + off))[t];
    float4 rv = ((const float4*)(resi + off))[t];
    hv.x += rv.x; hv.y += rv.y; hv.z += rv.z; hv.w += rv.w;
    ((float4*)(resout + off))[t] = hv;
    float s = hv.x*hv.x + hv.y*hv.y + hv.z*hv.z + hv.w*hv.w;
    s = blockReduceSum256(s);
    float sc = rsqrtf(s * (1.0f / DM) + EPSF);
    float4 wv = ((const float4*)w)[t];
    __half2* dst = (__half2*)(g_hn_h + off);
    dst[2 * t]     = __floats2half2_rn(hv.x * sc * wv.x, hv.y * sc * wv.y);
    dst[2 * t + 1] = __floats2half2_rn(hv.z * sc * wv.z, hv.w * sc * wv.w);
}

// ---------------- 2) FP16 tensor-core GEMM, 3-stage cp.async, split-precision output ----------------
#define AS_WORDS (128 * 20)
#define BS_WORDS (32 * 64)
#define GEMM_SMEM (3 * (AS_WORDS + BS_WORDS) * 4)
__global__ __launch_bounds__(256, 2) void gemm_fp16(
    const __half* __restrict__ A, const __half* __restrict__ Bm,
    float* __restrict__ C32, int ldc32, __half* __restrict__ C16, int ldc16,
    int split, int M, int N, int K)
{
    extern __shared__ unsigned smemBuf[];
    unsigned* AsBase = smemBuf;
    unsigned* BsBase = smemBuf + 3 * AS_WORDS;

    int tid = threadIdx.x;
    int lane = tid & 31, warp = tid >> 5;
    int warpRow = warp >> 2, warpCol = warp & 3;
    int rowBase = blockIdx.y * 128, colBase = blockIdx.x * 128;

    int aRow = tid >> 2, aChunk = (tid & 3);
    int bk = tid >> 4, bc = tid & 15;
    int gid = lane >> 2, tig = lane & 3;

    unsigned asBase = (unsigned)__cvta_generic_to_shared(AsBase);
    unsigned bsBase = (unsigned)__cvta_generic_to_shared(BsBase);

    const __half* aPtr0 = A + (size_t)(rowBase + aRow) * K + aChunk * 8;
    const __half* aPtr1 = A + (size_t)(rowBase + aRow + 64) * K + aChunk * 8;
    int cc = colBase + bc * 8;
    const __half* bPtr0 = Bm + (size_t)bk * N + cc;
    const __half* bPtr1 = Bm + (size_t)(bk + 16) * N + cc;
    int bsz = (cc < N) ? 16 : 0;

    unsigned da0 = asBase + (unsigned)((aRow * 20 + aChunk * 4) << 2);
    unsigned da1 = da0 + (64 * 20 << 2);
    unsigned db0 = bsBase + (unsigned)((bk * 64 + ((bc ^ (bk & 7)) * 4)) << 2);
    unsigned db1 = db0 + (16 * 64 << 2);

    int nIter = K >> 5;

    #define ISSUE(st, k0) do {                                                        \
        unsigned aoff = (unsigned)(st) * (AS_WORDS << 2);                             \
        unsigned boff = (unsigned)(st) * (BS_WORDS << 2);                             \
        asm volatile("cp.async.cg.shared.global [%0], [%1], 16;"                      \
                     :: "r"(da0 + aoff), "l"(aPtr0 + (k0)) : "memory");               \
        asm volatile("cp.async.cg.shared.global [%0], [%1], 16;"                      \
                     :: "r"(da1 + aoff), "l"(aPtr1 + (k0)) : "memory");               \
        asm volatile("cp.async.cg.shared.global [%0], [%1], 16, %2;"                  \
                     :: "r"(db0 + boff), "l"(bPtr0 + (size_t)(k0) * N), "r"(bsz) : "memory"); \
        asm volatile("cp.async.cg.shared.global [%0], [%1], 16, %2;"                  \
                     :: "r"(db1 + boff), "l"(bPtr1 + (size_t)(k0) * N), "r"(bsz) : "memory"); \
        asm volatile("cp.async.commit_group;" ::: "memory");                          \
    } while (0)

    float acc[4][4][4] = {};

    ISSUE(0, 0);
    if (nIter > 1) ISSUE(1, 32);

    int a_row_l = (lane & 7) + ((lane >> 3) & 1) * 8;
    int a_koff  = (lane >> 4) * 4;
    int b_krow  = ((lane >> 3) & 1) * 8 + (lane & 7);
    int b_nchl  = (lane >> 4);

    int st = 0;
    for (int it = 0; it < nIter; it++) {
        if (it + 1 < nIter)
            asm volatile("cp.async.wait_group 1;" ::: "memory");
        else
            asm volatile("cp.async.wait_group 0;" ::: "memory");
        __syncthreads();
        if (it + 2 < nIter) {
            int stN = st + 2; if (stN >= 3) stN -= 3;
            ISSUE(stN, (it + 2) << 5);
        }

        unsigned aStage = asBase + (unsigned)(st * (AS_WORDS << 2));
        unsigned bStage = bsBase + (unsigned)(st * (BS_WORDS << 2));

        #pragma unroll
        for (int ks = 0; ks < 2; ks++) {
            unsigned a[4][4], bfr[2][4];
            #pragma unroll
            for (int i = 0; i < 4; i++) {
                int row = warpRow * 64 + i * 16 + a_row_l;
                unsigned addr = aStage + (unsigned)((row * 20 + ks * 8 + a_koff) << 2);
                LDSM_X4(a[i], addr);
            }
            #pragma unroll
            for (int j2 = 0; j2 < 2; j2++) {
                int kk = ks * 16 + b_krow;
                int nch = warpCol * 4 + j2 * 2 + b_nchl;
                unsigned addr = bStage + (unsigned)((kk * 64 + ((nch ^ (kk & 7)) * 4)) << 2);
                LDSM_X4T(bfr[j2], addr);
            }
            #pragma unroll
            for (int i = 0; i < 4; i++)
                #pragma unroll
                for (int j = 0; j < 4; j++) {
                    unsigned bb[2] = { bfr[j >> 1][(j & 1) * 2], bfr[j >> 1][(j & 1) * 2 + 1] };
                    mma_fp16(acc[i][j], a[i], bb);
                }
        }
        st++; if (st >= 3) st -= 3;
    }
    #undef ISSUE

    #pragma unroll
    for (int i = 0; i < 4; i++) {
        int r0 = rowBase + warpRow * 64 + i * 16 + gid;
        #pragma unroll
        for (int j = 0; j < 4; j++) {
            int ccj = colBase + warpCol * 32 + j * 8 + tig * 2;
            if (ccj < N) {
                if (ccj < split) {
                    *(float2*)(C32 + (size_t)r0 * ldc32 + ccj)       = make_float2(acc[i][j][0], acc[i][j][1]);
                    *(float2*)(C32 + (size_t)(r0 + 8) * ldc32 + ccj) = make_float2(acc[i][j][2], acc[i][j][3]);
                } else {
                    int ch = ccj - split;
                    *(__half2*)(C16 + (size_t)r0 * ldc16 + ch)       = __floats2half2_rn(acc[i][j][0], acc[i][j][1]);
                    *(__half2*)(C16 + (size_t)(r0 + 8) * ldc16 + ch) = __floats2half2_rn(acc[i][j][2], acc[i][j][3]);
                }
            }
        }
    }
}

// ---------------- 3) depthwise causal conv + bias + SiLU (fp16 in/out) ----------------
__global__ __launch_bounds__(256) void k_conv(
    const float* __restrict__ cw, const float* __restrict__ cb)
{
    int ch = blockIdx.x * 256 + threadIdx.x;   // 0..2303
    int rb = blockIdx.y * 64;
    int b = rb >> 12;
    int l0 = rb & 4095;
    float w0 = cw[ch], w1 = cw[NCH + ch], w2 = cw[2 * NCH + ch], w3 = cw[3 * NCH + ch];
    float bias = cb[ch];
    const __half* src = g_zxh + ch;
    float x1 = 0.f, x2 = 0.f, x3 = 0.f;
    if (l0 >= 1) x1 = __half2float(src[(size_t)(b * LL + l0 - 1) * NPJH]);
    if (l0 >= 2) x2 = __half2float(src[(size_t)(b * LL + l0 - 2) * NPJH]);
    if (l0 >= 3) x3 = __half2float(src[(size_t)(b * LL + l0 - 3) * NPJH]);
    #pragma unroll 4
    for (int i = 0; i < 64; i++) {
        int l = l0 + i;
        float cur = __half2float(src[(size_t)(b * LL + l) * NPJH]);
        float v = siluf(bias + w3 * cur + w2 * x1 + w1 * x2 + w0 * x3);
        g_xBCh[(size_t)(b * LL + l) * NCH + ch] = __float2half(v);
        x3 = x2; x2 = x1; x1 = cur;
    }
}

// ---------------- 4) dt = softplus(raw+bias); per-chunk cumsum of dt*A ----------------
__global__ __launch_bounds__(256) void k_dtscan(
    const float* __restrict__ dtb, const float* __restrict__ alog)
{
    int bc = blockIdx.x, h = blockIdx.y, l = threadIdx.x;
    int b = bc >> 4, c = bc & 15;
    int row = b * LL + c * CHK + l;
    float raw = __half2float(g_zxh[(size_t)row * NPJH + NCH + h]) + dtb[h];
    float dt = softplusf(raw);
    g_dt[row * HH + h] = dt;
    float v = -dt * expf(alog[h]);
    __shared__ float sb[CHK];
    sb[l] = v;
    __syncthreads();
    for (int o = 1; o < CHK; o <<= 1) {
        float add = (l >= o) ? sb[l - o] : 0.f;
        __syncthreads();
        sb[l] += add;
        __syncthreads();
    }
    g_Acum[(bc * HH + h) * CHK + l] = sb[l];
    if (l == CHK - 1) g_cdec[bc * HH + h] = expf(sb[l]);
}

// ---------------- 5) S via MMA: S[s,l] = sum_n B[s,n]*C[l,n] ----------------
__global__ __launch_bounds__(256) void k_S()
{
    int bc = blockIdx.z;
    int b = bc >> 4, c = bc & 15;
    int rowb = b * LL + c * CHK;
    int s0b = blockIdx.x * 128, l0b = blockIdx.y * 128;
    __shared__ __half As[128 * 40];
    __shared__ __half Bt[32 * 136];
    int t = threadIdx.x;
    int lane = t & 31, warp = t >> 5;
    int warpRow = warp >> 2, warpCol = warp & 3;
    int a_row_l = (lane & 7) + ((lane >> 3) & 1) * 8;
    int a_koff  = (lane >> 4) * 8;   // halves
    int b_krow  = ((lane >> 3) & 1) * 8 + (lane & 7);
    int b_nchl  = (lane >> 4);
    int gid = lane >> 2, tig = lane & 3;
    unsigned asB = (unsigned)__cvta_generic_to_shared(As);
    unsigned btB = (unsigned)__cvta_generic_to_shared(Bt);
    const __half2* xbc2 = (const __half2*)g_xBCh;

    float acc[4][4][4] = {};
    for (int kt = 0; kt < 4; kt++) {
        for (int idx = t; idx < 2048; idx += 256) {
            int n2 = idx & 15, s = idx >> 4;
            __half2 v = xbc2[(size_t)(rowb + s0b + s) * (NCH / 2) + (DIN / 2) + kt * 16 + n2];
            *(__half2*)&As[s * 40 + n2 * 2] = v;
        }
        for (int idx = t; idx < 2048; idx += 256) {
            int n2 = idx & 15, l = idx >> 4;
            __half2 v = xbc2[(size_t)(rowb + l0b + l) * (NCH / 2) + (DIN + NSt) / 2 + kt * 16 + n2];
            Bt[(n2 * 2) * 136 + l]     = __low2half(v);
            Bt[(n2 * 2 + 1) * 136 + l] = __high2half(v);
        }
        __syncthreads();
        #pragma unroll
        for (int ks = 0; ks < 2; ks++) {
            unsigned a[4][4], bfr[2][4];
            #pragma unroll
            for (int i = 0; i < 4; i++) {
                int row = warpRow * 64 + i * 16 + a_row_l;
                unsigned addr = asB + (unsigned)((row * 40 + ks * 16 + a_koff) * 2);
                LDSM_X4(a[i], addr);
            }
            #pragma unroll
            for (int j2 = 0; j2 < 2; j2++) {
                int kk = ks * 16 + b_krow;
                int nch = warpCol * 4 + j2 * 2 + b_nchl;
                unsigned addr = btB + (unsigned)((kk * 136 + nch * 8) * 2);
                LDSM_X4T(bfr[j2], addr);
            }
            #pragma unroll
            for (int i = 0; i < 4; i++)
                #pragma unroll
                for (int j = 0; j < 4; j++) {
                    unsigned bb[2] = { bfr[j >> 1][(j & 1) * 2], bfr[j >> 1][(j & 1) * 2 + 1] };
                    mma_fp16(acc[i][j], a[i], bb);
                }
        }
        __syncthreads();
    }
    __half* out = g_S_h + (size_t)bc * CHK * CHK;
    #pragma unroll
    for (int i = 0; i < 4; i++) {
        int r0 = s0b + warpRow * 64 + i * 16 + gid;
        #pragma unroll
        for (int j = 0; j < 4; j++) {
            int col = l0b + warpCol * 32 + j * 8 + tig * 2;
            *(__half2*)&out[(size_t)r0 * CHK + col]       = __floats2half2_rn(acc[i][j][0], acc[i][j][1]);
            *(__half2*)&out[(size_t)(r0 + 8) * CHK + col] = __floats2half2_rn(acc[i][j][2], acc[i][j][3]);
        }
    }
}

// ---------------- 6) states via MMA: states[p,n] = sum_l Xdt[l,p]*Bw[l,n] ----------------
__global__ __launch_bounds__(256) void k_states()
{
    int bc = blockIdx.x, h = blockIdx.y;
    int b = bc >> 4, c = bc & 15;
    int rowb = b * LL + c * CHK;
    const float* Ac = g_Acum + (bc * HH + h) * CHK;
    __shared__ float wsm[32];
    __shared__ __half Xt[64 * 40];
    __shared__ __half Bw[32 * 136];
    int t = threadIdx.x;
    int lane = t & 31, warp = t >> 5;
    int mb = (warp >> 1) * 16, nb = (warp & 1) * 64;
    int a_row_l = (lane & 7) + ((lane >> 3) & 1) * 8;
    int a_koff  = (lane >> 4) * 8;
    int b_krow  = ((lane >> 3) & 1) * 8 + (lane & 7);
    int b_nchl  = (lane >> 4);
    int gid = lane >> 2, tig = lane & 3;
    unsigned xtB = (unsigned)__cvta_generic_to_shared(Xt);
    unsigned bwB = (unsigned)__cvta_generic_to_shared(Bw);

    float acc[8][4] = {};
    float alast = Ac[CHK - 1];
    const __half2* xbc2 = (const __half2*)g_xBCh;
    for (int lt = 0; lt < 8; lt++) {
        if (t < 32) wsm[t] = __expf(alast - Ac[lt * 32 + t]);
        __syncthreads();
        for (int idx = t; idx < 2048; idx += 256) {
            int n2 = idx & 63, ll = idx >> 6;
            int row = rowb + lt * 32 + ll;
            __half2 v = xbc2[(size_t)row * (NCH / 2) + (DIN / 2) + n2];
            __half2 w = __float2half2_rn(wsm[ll]);
            *(__half2*)&Bw[ll * 136 + n2 * 2] = __hmul2(v, w);
        }
        for (int idx = t; idx < 1024; idx += 256) {
            int p2 = idx & 31, ll = idx >> 5;
            int row = rowb + lt * 32 + ll;
            __half2 v = xbc2[(size_t)row * (NCH / 2) + h * 32 + p2];
            __half2 d = __float2half2_rn(g_dt[row * HH + h]);
            __half2 r = __hmul2(v, d);
            Xt[(p2 * 2) * 40 + ll]     = __low2half(r);
            Xt[(p2 * 2 + 1) * 40 + ll] = __high2half(r);
        }
        __syncthreads();
        #pragma unroll
        for (int ks = 0; ks < 2; ks++) {
            unsigned a[4], bfr[4][4];
            {
                int row = mb + a_row_l;
                unsigned addr = xtB + (unsigned)((row * 40 + ks * 16 + a_koff) * 2);
                LDSM_X4(a, addr);
            }
            #pragma unroll
            for (int j2 = 0; j2 < 4; j2++) {
                int kk = ks * 16 + b_krow;
                int nch = (nb >> 3) + j2 * 2 + b_nchl;
                unsigned addr = bwB + (unsigned)((kk * 136 + nch * 8) * 2);
                LDSM_X4T(bfr[j2], addr);
            }
            #pragma unroll
            for (int j = 0; j < 8; j++) {
                unsigned bb[2] = { bfr[j >> 1][(j & 1) * 2], bfr[j >> 1][(j & 1) * 2 + 1] };
                mma_fp16(acc[j], a, bb);
            }
        }
        __syncthreads();
    }
    float* out = g_states + (size_t)(bc * HH + h) * PP * NSt;
    #pragma unroll
    for (int j = 0; j < 8; j++) {
        int p0 = mb + gid;
        int nn = nb + j * 8 + tig * 2;
        *(float2*)&out[p0 * NSt + nn]       = make_float2(acc[j][0], acc[j][1]);
        *(float2*)&out[(p0 + 8) * NSt + nn] = make_float2(acc[j][2], acc[j][3]);
    }
}

// ---------------- 7) inter-chunk recurrence (fp32 carry, fp16 prev out) ----------------
__global__ __launch_bounds__(256) void k_scan()
{
    int tid = blockIdx.x * 256 + threadIdx.x;  // 524288
    int n = tid & 127;
    int p = (tid >> 7) & 63;
    int h = (tid >> 13) & 31;
    int b = tid >> 18;
    float carry = 0.f;
    for (int c = 0; c < NC; c++) {
        int bc = b * NC + c;
        size_t idx = (size_t)(bc * HH + h) * PP * NSt + p * NSt + n;
        float dec = g_cdec[bc * HH + h];
        g_prev_h[idx] = __float2half(carry);
        carry = carry * dec + g_states[idx];
    }
}

// ---------------- 8) Y = Y_off + Y_diag + D*x via MMA ----------------
__global__ __launch_bounds__(256) void k_Y(const float* __restrict__ Dp)
{
    int bc = blockIdx.x, h = blockIdx.y;
    int b = bc >> 4, c = bc & 15;
    int rowb = b * LL + c * CHK;
    int t = threadIdx.x;
    int lane = t & 31, warp = t >> 5;
    int mb = (warp >> 1) * 64, nb = (warp & 1) * 32;

    __shared__ float Asm[CHK];
    __shared__ float es_all[CHK];
    __shared__ __half Am[256 * 40];
    __shared__ __half Bt[32 * 72];

    const float* Ac = g_Acum + (bc * HH + h) * CHK;
    Asm[t] = Ac[t];

    int a_row_l = (lane & 7) + ((lane >> 3) & 1) * 8;
    int a_koff  = (lane >> 4) * 8;
    int b_krow  = ((lane >> 3) & 1) * 8 + (lane & 7);
    int b_nchl  = (lane >> 4);
    int gid = lane >> 2, tig = lane & 3;
    unsigned amB = (unsigned)__cvta_generic_to_shared(Am);
    unsigned btB = (unsigned)__cvta_generic_to_shared(Bt);

    float acc[4][4][4] = {};
    const __half2* xbc2 = (const __half2*)g_xBCh;
    const __half* prevp = g_prev_h + (size_t)(bc * HH + h) * PP * NSt;
    __syncthreads();
    es_all[t] = __expf(Asm[t & ~31] - Asm[t]);
    float alv = Asm[t];

    // ---- off phase: k = n_state, 4 tiles of 32 ----
    for (int nt = 0; nt < 4; nt++) {
        for (int idx = t; idx < 4096; idx += 256) {
            int kk2 = idx & 15, l = idx >> 4;
            __half2 v = xbc2[(size_t)(rowb + l) * (NCH / 2) + (DIN + NSt) / 2 + nt * 16 + kk2];
            *(__half2*)&Am[l * 40 + kk2 * 2] = v;
        }
        for (int idx = t; idx < 1024; idx += 256) {
            int kk2 = idx & 15, p = idx >> 4;
            __half2 v = *(const __half2*)&prevp[p * NSt + nt * 32 + kk2 * 2];
            Bt[(kk2 * 2) * 72 + p]     = __low2half(v);
            Bt[(kk2 * 2 + 1) * 72 + p] = __high2half(v);
        }
        __syncthreads();
        #pragma unroll
        for (int ks = 0; ks < 2; ks++) {
            unsigned a[4][4], bfr[2][4];
            #pragma unroll
            for (int i = 0; i < 4; i++) {
                int row = mb + i * 16 + a_row_l;
                unsigned addr = amB + (unsigned)((row * 40 + ks * 16 + a_koff) * 2);
                LDSM_X4(a[i], addr);
            }
            #pragma unroll
            for (int j2 = 0; j2 < 2; j2++) {
                int kk = ks * 16 + b_krow;
                int nch = (nb >> 3) + j2 * 2 + b_nchl;
                unsigned addr = btB + (unsigned)((kk * 72 + nch * 8) * 2);
                LDSM_X4T(bfr[j2], addr);
            }
            #pragma unroll
            for (int i = 0; i < 4; i++)
                #pragma unroll
                for (int j = 0; j < 4; j++) {
                    unsigned bb[2] = { bfr[j >> 1][(j & 1) * 2], bfr[j >> 1][(j & 1) * 2 + 1] };
                    mma_fp16(acc[i][j], a[i], bb);
                }
        }
        __syncthreads();
    }
    #pragma unroll
    for (int i = 0; i < 4; i++) {
        int l0 = mb + i * 16 + gid;
        float e0 = __expf(Asm[l0]);
        float e1 = __expf(Asm[l0 + 8]);
        #pragma unroll
        for (int j = 0; j < 4; j++) {
            acc[i][j][0] *= e0; acc[i][j][1] *= e0;
            acc[i][j][2] *= e1; acc[i][j][3] *= e1;
        }
    }

    // ---- diag phase: k = s, 8 tiles of 32 ----
    const __half* Sp = g_S_h + (size_t)bc * CHK * CHK;
    for (int st8 = 0; st8 < 8; st8++) {
        int s0 = st8 * 32;
        if (t >= s0) {
            float el = __expf(alv - Asm[s0]);
            #pragma unroll
            for (int g4 = 0; g4 < 4; g4++) {
                float w[8];
                #pragma unroll
                for (int k = 0; k < 8; k++) {
                    int s = s0 + g4 * 8 + k;
                    w[k] = (s <= t) ? __half2float(Sp[(size_t)s * CHK + t]) * (el * es_all[s]) : 0.f;
                }
                uint4 u;
                *(__half2*)&u.x = __floats2half2_rn(w[0], w[1]);
                *(__half2*)&u.y = __floats2half2_rn(w[2], w[3]);
                *(__half2*)&u.z = __floats2half2_rn(w[4], w[5]);
                *(__half2*)&u.w = __floats2half2_rn(w[6], w[7]);
                *(uint4*)&Am[t * 40 + g4 * 8] = u;
            }
        } else {
            uint4 z = make_uint4(0, 0, 0, 0);
            #pragma unroll
            for (int g4 = 0; g4 < 4; g4++) *(uint4*)&Am[t * 40 + g4 * 8] = z;
        }
        for (int idx = t; idx < 1024; idx += 256) {
            int p2 = idx & 31, ss = idx >> 5;
            int row = rowb + s0 + ss;
            __half2 v = xbc2[(size_t)row * (NCH / 2) + h * 32 + p2];
            __half2 d = __float2half2_rn(g_dt[row * HH + h]);
            *(__half2*)&Bt[ss * 72 + p2 * 2] = __hmul2(v, d);
        }
        __syncthreads();
        if (mb + 64 > s0) {
            #pragma unroll
            for (int ks = 0; ks < 2; ks++) {
                unsigned a[4][4], bfr[2][4];
                #pragma unroll
                for (int i = 0; i < 4; i++) {
                    int row = mb + i * 16 + a_row_l;
                    unsigned addr = amB + (unsigned)((row * 40 + ks * 16 + a_koff) * 2);
                    LDSM_X4(a[i], addr);
                }
                #pragma unroll
                for (int j2 = 0; j2 < 2; j2++) {
                    int kk = ks * 16 + b_krow;
                    int nch = (nb >> 3) + j2 * 2 + b_nchl;
                    unsigned addr = btB + (unsigned)((kk * 72 + nch * 8) * 2);
                    LDSM_X4T(bfr[j2], addr);
                }
                #pragma unroll
                for (int i = 0; i < 4; i++)
                    #pragma unroll
                    for (int j = 0; j < 4; j++) {
                        unsigned bb[2] = { bfr[j >> 1][(j & 1) * 2], bfr[j >> 1][(j & 1) * 2 + 1] };
                        mma_fp16(acc[i][j], a[i], bb);
                    }
            }
        }
        __syncthreads();
    }

    // ---- skip term (fp16 x) + store fp16 ----
    float dh = Dp[h];
    #pragma unroll
    for (int i = 0; i < 4; i++) {
        int l0 = mb + i * 16 + gid;
        #pragma unroll
        for (int j = 0; j < 4; j++) {
            int p = nb + j * 8 + tig * 2;
            #pragma unroll
            for (int r = 0; r < 2; r++) {
                int row = rowb + l0 + r * 8;
                float2 xv = __half22float2(*(const __half2*)&g_xBCh[(size_t)row * NCH + h * PP + p]);
                *(__half2*)&g_y_h[(size_t)row * DIN + h * PP + p] =
                    __floats2half2_rn(acc[i][j][r * 2 + 0] + dh * xv.x,
                                      acc[i][j][r * 2 + 1] + dh * xv.y);
            }
        }
    }
}

// ---------------- 9) gated SiLU + RMSNorm over 2048 (fp16 in/out) ----------------
__global__ __launch_bounds__(256) void k_gatednorm(const float* __restrict__ gw)
{
    int row = blockIdx.x, t = threadIdx.x;
    size_t yo = (size_t)row * DIN;
    float4 vv[2];
    float ssum = 0.f;
    #pragma unroll
    for (int k = 0; k < 2; k++) {
        uint2 u = *(const uint2*)&g_y_h[yo + (size_t)(k * 256 + t) * 4];
        float2 ya = __half22float2(*(__half2*)&u.x), yb = __half22float2(*(__half2*)&u.y);
        float4 zv = ((const float4*)(g_zx + yo))[k * 256 + t];
        float4 v;
        v.x = ya.x * siluf(zv.x); v.y = ya.y * siluf(zv.y);
        v.z = yb.x * siluf(zv.z); v.w = yb.y * siluf(zv.w);
        vv[k] = v;
        ssum += v.x * v.x + v.y * v.y + v.z * v.z + v.w * v.w;
    }
    ssum = blockReduceSum256(ssum);
    float sc = rsqrtf(ssum * (1.0f / DIN) + EPSF);
    __half2* dst = (__half2*)(g_yn_h + yo);
    #pragma unroll
    for (int k = 0; k < 2; k++) {
        float4 w = ((const float4*)gw)[k * 256 + t];
        float4 v = vv[k];
        dst[2 * (k * 256 + t)]     = __floats2half2_rn(v.x * sc * w.x, v.y * sc * w.y);
        dst[2 * (k * 256 + t) + 1] = __floats2half2_rn(v.z * sc * w.z, v.w * sc * w.w);
    }
}

// ---------------- launch (2 streams: overlap independent stages) ----------------
extern "C" void kernel_launch(void* const* d_in, const int* in_sizes, int n_in,
                              void* d_out, int out_size)
{
    const float* hid  = (const float*)d_in[0];
    const float* resi = (const float*)d_in[1];
    const float* nw   = (const float*)d_in[2];
    const float* inw  = (const float*)d_in[3];
    const float* cw   = (const float*)d_in[4];
    const float* cb   = (const float*)d_in[5];
    const float* dtb  = (const float*)d_in[6];
    const float* alog = (const float*)d_in[7];
    const float* Dp   = (const float*)d_in[8];
    const float* gw   = (const float*)d_in[9];
    const float* ow   = (const float*)d_in[10];

    float* out    = (float*)d_out;
    float* resout = out + (size_t)ROWS * DM;

    float *p_zx;
    __half *p_hn, *p_zxh, *p_yn, *p_w1, *p_w2;
    cudaGetSymbolAddress((void**)&p_hn, g_hn_h);
    cudaGetSymbolAddress((void**)&p_zx, g_zx);
    cudaGetSymbolAddress((void**)&p_zxh, g_zxh);
    cudaGetSymbolAddress((void**)&p_yn, g_yn_h);
    cudaGetSymbolAddress((void**)&p_w1, g_w1h);
    cudaGetSymbolAddress((void**)&p_w2, g_w2h);

    cudaFuncSetAttribute(gemm_fp16, cudaFuncAttributeMaxDynamicSharedMemorySize, GEMM_SMEM);

    // Side stream + events. Created per call, never destroyed (kernel_launch runs
    // only a handful of times; destroying a capturing side stream mid-capture
    // would poison the capture). Non-blocking to avoid legacy-stream coupling.
    cudaStream_t s1;
    cudaStreamCreateWithFlags(&s1, cudaStreamNonBlocking);
    cudaEvent_t eF, eW, eG, eDT, eCV, eS;
    cudaEventCreateWithFlags(&eF,  cudaEventDisableTiming);
    cudaEventCreateWithFlags(&eW,  cudaEventDisableTiming);
    cudaEventCreateWithFlags(&eG,  cudaEventDisableTiming);
    cudaEventCreateWithFlags(&eDT, cudaEventDisableTiming);
    cudaEventCreateWithFlags(&eCV, cudaEventDisableTiming);
    cudaEventCreateWithFlags(&eS,  cudaEventDisableTiming);

    // fork: weight rounding on s1, addnorm+w1 on main
    cudaEventRecord(eF, 0);
    cudaStreamWaitEvent(s1, eF, 0);
    k_round_h<<<(DIN * DM / 4 + 255) / 256, 256, 0, s1>>>(ow, p_w2, DIN * DM / 4);
    k_round_h<<<(DM * NPJ / 4 + 255) / 256, 256, 0, s1>>>(inw, p_w1, DM * NPJ / 4);
    cudaEventRecord(eW, s1);

    k_addnorm<<<ROWS, 256>>>(hid, resi, nw, resout);
    cudaStreamWaitEvent(0, eW, 0);   // w1 ready
    gemm_fp16<<<dim3((NPJ + 127) / 128, ROWS / 128), 256, GEMM_SMEM>>>(
        p_hn, p_w1, p_zx, DIN, p_zxh, NPJH, DIN, ROWS, NPJ, DM);
    cudaEventRecord(eG, 0);

    // dtscan on s1 concurrent with conv on main
    cudaStreamWaitEvent(s1, eG, 0);
    k_dtscan<<<dim3(NBC, HH), 256, 0, s1>>>(dtb, alog);
    cudaEventRecord(eDT, s1);

    k_conv<<<dim3(NCH / 256, ROWS / 64), 256>>>(cw, cb);
    cudaEventRecord(eCV, 0);

    // k_S on s1 (needs conv only), concurrent with k_states+k_scan on main
    cudaStreamWaitEvent(s1, eCV, 0);
    k_S<<<dim3(2, 2, NBC), 256, 0, s1>>>();
    cudaEventRecord(eS, s1);

    cudaStreamWaitEvent(0, eDT, 0);  // states needs dt/Acum
    k_states<<<dim3(NBC, HH), 256>>>();
    k_scan<<<(BB * HH * PP * NSt) / 256, 256>>>();

    cudaStreamWaitEvent(0, eS, 0);   // Y needs S
    k_Y<<<dim3(NBC, HH), 256>>>(Dp);
    k_gatednorm<<<ROWS, 256>>>(gw);
    gemm_fp16<<<dim3(DM / 128, ROWS / 128), 256, GEMM_SMEM>>>(
        p_yn, p_w2, out, DM, p_zxh, 1, DM, ROWS, DM, DIN);
}